// round 1
// baseline (speedup 1.0000x reference)
#include <cuda_runtime.h>

#define D 128
#define MAXN_NET 100000
#define MAXN_DAG 50000

// ---------------- device scratch (allocation-free rule: __device__ globals) ---
__device__ __align__(16) float g_h_net[MAXN_NET * D];
__device__ __align__(16) float g_agg_net[MAXN_NET * D];
__device__ float g_deg_net[MAXN_NET];
__device__ __align__(16) float g_h_dag[MAXN_DAG * D];
__device__ __align__(16) float g_agg_dag[MAXN_DAG * D];
__device__ float g_deg_dag[MAXN_DAG];
__device__ __align__(16) float g_acc[2 * D];   // [0:128) net mean-acc, [128:256) dag

// ---------------- helpers -----------------------------------------------------
__device__ __forceinline__ void red_add_v4(float* p, float4 v) {
    asm volatile("red.global.add.v4.f32 [%0], {%1,%2,%3,%4};"
                 :: "l"(p), "f"(v.x), "f"(v.y), "f"(v.z), "f"(v.w) : "memory");
}

// ---------------- tiny utility kernels ----------------------------------------
__global__ void zero4_kernel(float4* p, int n4) {
    for (int i = blockIdx.x * blockDim.x + threadIdx.x; i < n4;
         i += gridDim.x * blockDim.x)
        p[i] = make_float4(0.f, 0.f, 0.f, 0.f);
}

__global__ void fill1_kernel(float* p, int n) {
    int i = blockIdx.x * blockDim.x + threadIdx.x;
    if (i < n) p[i] = 1.0f;                  // self-loop weight
}

__global__ void deg_acc_kernel(const int* __restrict__ ei,
                               const float* __restrict__ ew,
                               float* __restrict__ deg, int E) {
    int e = blockIdx.x * blockDim.x + threadIdx.x;
    if (e < E) atomicAdd(&deg[ei[E + e]], ew[e]);   // dst = ei[E+e]
}

__global__ void deg_inv_kernel(float* deg, int N) {
    int i = blockIdx.x * blockDim.x + threadIdx.x;
    if (i < N) {
        float d = deg[i];
        deg[i] = (d > 0.f) ? rsqrtf(d) : 0.f;
    }
}

// ---------------- GEMM: H[N,128] = X[N,128] @ W[128,128] ----------------------
// 64-row tile per block, W + X-tile in SMEM (96KB dyn), 256 thr, 8x4 microtile.
__global__ void gemm128_kernel(const float* __restrict__ X,
                               const float* __restrict__ W,
                               float* __restrict__ H, int N) {
    extern __shared__ float sm[];
    float* As = sm;             // 64 * 128
    float* Bs = sm + 64 * D;    // 128 * 128
    const int tid = threadIdx.x;
    const int row0 = blockIdx.x * 64;

    // load W (4096 float4)
    const float4* W4 = (const float4*)W;
    float4* Bs4 = (float4*)Bs;
#pragma unroll
    for (int i = 0; i < 16; i++) Bs4[tid + 256 * i] = W4[tid + 256 * i];

    // load X tile (2048 float4), zero-padded past N
    float4* As4 = (float4*)As;
#pragma unroll
    for (int i = 0; i < 8; i++) {
        int idx = tid + 256 * i;
        int r = idx >> 5, c = idx & 31;
        int grow = row0 + r;
        float4 v = make_float4(0.f, 0.f, 0.f, 0.f);
        if (grow < N) v = ((const float4*)X)[grow * 32 + c];
        As4[idx] = v;
    }
    __syncthreads();

    const int tx = tid & 31;    // col group: 4 cols at tx*4
    const int ty = tid >> 5;    // row group: 8 rows at ty*8
    float acc[8][4];
#pragma unroll
    for (int r = 0; r < 8; r++)
#pragma unroll
        for (int c = 0; c < 4; c++) acc[r][c] = 0.f;

#pragma unroll 4
    for (int k = 0; k < D; k++) {
        float4 b4 = ((const float4*)(Bs + k * D))[tx];
#pragma unroll
        for (int r = 0; r < 8; r++) {
            float a = As[(ty * 8 + r) * D + k];   // warp-broadcast
            acc[r][0] += a * b4.x;
            acc[r][1] += a * b4.y;
            acc[r][2] += a * b4.z;
            acc[r][3] += a * b4.w;
        }
    }

#pragma unroll
    for (int r = 0; r < 8; r++) {
        int grow = row0 + ty * 8 + r;
        if (grow < N)
            ((float4*)(H + grow * D))[tx] =
                make_float4(acc[r][0], acc[r][1], acc[r][2], acc[r][3]);
    }
}

// ---------------- edge scatter: agg[dst] += h[src] * norm ---------------------
// one warp per edge; lane handles 4 contiguous floats; vector RED (no return).
__global__ void scatter_kernel(const int* __restrict__ ei,
                               const float* __restrict__ ew,
                               const float* __restrict__ dinv,
                               const float* __restrict__ H,
                               float* __restrict__ AGG, int E) {
    int w = (blockIdx.x * blockDim.x + threadIdx.x) >> 5;
    int lane = threadIdx.x & 31;
    if (w >= E) return;
    int src = ei[w];
    int dst = ei[E + w];
    float norm = dinv[src] * ew[w] * dinv[dst];
    float4 v = ((const float4*)(H + src * D))[lane];
    v.x *= norm; v.y *= norm; v.z *= norm; v.w *= norm;
    red_add_v4(AGG + dst * D + lane * 4, v);
}

// ---------------- epilogue: +self-loop, +bias, relu, l2norm, mean-accumulate --
__global__ void epilogue_kernel(const float* __restrict__ AGG,
                                const float* __restrict__ H,
                                const float* __restrict__ dinv,
                                const float* __restrict__ b,
                                float* __restrict__ acc_out, int N) {
    int lane = threadIdx.x & 31;
    int warp = (blockIdx.x * blockDim.x + threadIdx.x) >> 5;
    int nwarps = (gridDim.x * blockDim.x) >> 5;
    float4 bb = ((const float4*)b)[lane];
    float4 acc = make_float4(0.f, 0.f, 0.f, 0.f);

    for (int i = warp; i < N; i += nwarps) {
        float di = dinv[i];
        float dd = di * di;                               // self-loop norm
        float4 a = ((const float4*)(AGG + i * D))[lane];
        float4 hh = ((const float4*)(H + i * D))[lane];
        float4 v;
        v.x = fmaxf(a.x + hh.x * dd + bb.x, 0.f);
        v.y = fmaxf(a.y + hh.y * dd + bb.y, 0.f);
        v.z = fmaxf(a.z + hh.z * dd + bb.z, 0.f);
        v.w = fmaxf(a.w + hh.w * dd + bb.w, 0.f);
        float s = v.x * v.x + v.y * v.y + v.z * v.z + v.w * v.w;
#pragma unroll
        for (int o = 16; o; o >>= 1) s += __shfl_xor_sync(0xFFFFFFFFu, s, o);
        float scale = 1.0f / fmaxf(sqrtf(s), 1e-12f);     // l2norm
        acc.x += v.x * scale;
        acc.y += v.y * scale;
        acc.z += v.z * scale;
        acc.w += v.w * scale;
    }
    float* ao = acc_out + lane * 4;
    atomicAdd(ao + 0, acc.x);
    atomicAdd(ao + 1, acc.y);
    atomicAdd(ao + 2, acc.z);
    atomicAdd(ao + 3, acc.w);
}

// ---------------- final MLP: concat means -> 64 relu -> 1 ---------------------
__global__ void final_mlp_kernel(const float* __restrict__ acc,
                                 const float* __restrict__ W1,
                                 const float* __restrict__ b1,
                                 const float* __restrict__ W2,
                                 const float* __restrict__ b2,
                                 float invNnet, float invNdag,
                                 float* __restrict__ out) {
    __shared__ float c[256];
    __shared__ float h1[64];
    int t = threadIdx.x;   // 256 threads
    c[t] = acc[t] * (t < 128 ? invNnet : invNdag);
    __syncthreads();
    if (t < 64) {
        float s = b1[t];
#pragma unroll 8
        for (int i = 0; i < 256; i++) s += c[i] * W1[i * 64 + t];
        h1[t] = fmaxf(s, 0.f);
    }
    __syncthreads();
    if (t == 0) {
        float s = b2[0];
#pragma unroll
        for (int j = 0; j < 64; j++) s += h1[j] * W2[j];
        out[0] = s;
    }
}

// ---------------- launch -------------------------------------------------------
extern "C" void kernel_launch(void* const* d_in, const int* in_sizes, int n_in,
                              void* d_out, int out_size) {
    const float* net_feat = (const float*)d_in[0];
    const int*   net_ei   = (const int*)  d_in[1];
    const float* net_ew   = (const float*)d_in[2];
    const float* dag_feat = (const float*)d_in[3];
    const int*   dag_ei   = (const int*)  d_in[4];
    const float* dag_ew   = (const float*)d_in[5];
    const float* W_net    = (const float*)d_in[6];
    const float* b_net    = (const float*)d_in[7];
    const float* W_dag    = (const float*)d_in[8];
    const float* b_dag    = (const float*)d_in[9];
    const float* W1       = (const float*)d_in[10];
    const float* b1       = (const float*)d_in[11];
    const float* W2       = (const float*)d_in[12];
    const float* b2       = (const float*)d_in[13];
    float* out = (float*)d_out;

    const int N_net = in_sizes[0] / D;
    const int E_net = in_sizes[2];
    const int N_dag = in_sizes[3] / D;
    const int E_dag = in_sizes[5];

    void *p;
    cudaGetSymbolAddress(&p, g_h_net);   float* h_net   = (float*)p;
    cudaGetSymbolAddress(&p, g_agg_net); float* agg_net = (float*)p;
    cudaGetSymbolAddress(&p, g_deg_net); float* deg_net = (float*)p;
    cudaGetSymbolAddress(&p, g_h_dag);   float* h_dag   = (float*)p;
    cudaGetSymbolAddress(&p, g_agg_dag); float* agg_dag = (float*)p;
    cudaGetSymbolAddress(&p, g_deg_dag); float* deg_dag = (float*)p;
    cudaGetSymbolAddress(&p, g_acc);     float* acc     = (float*)p;

    const int smem_gemm = (64 * D + D * D) * (int)sizeof(float);  // 96 KB
    cudaFuncSetAttribute(gemm128_kernel,
                         cudaFuncAttributeMaxDynamicSharedMemorySize, smem_gemm);

    // --- zero aggregation buffers + mean accumulator ---
    zero4_kernel<<<2048, 256>>>((float4*)agg_net, N_net * (D / 4));
    zero4_kernel<<<1024, 256>>>((float4*)agg_dag, N_dag * (D / 4));
    zero4_kernel<<<1, 64>>>((float4*)acc, 2 * D / 4);

    // --- degrees (self-loop contributes 1) -> dinv ---
    fill1_kernel<<<(N_net + 255) / 256, 256>>>(deg_net, N_net);
    fill1_kernel<<<(N_dag + 255) / 256, 256>>>(deg_dag, N_dag);
    deg_acc_kernel<<<(E_net + 255) / 256, 256>>>(net_ei, net_ew, deg_net, E_net);
    deg_acc_kernel<<<(E_dag + 255) / 256, 256>>>(dag_ei, dag_ew, deg_dag, E_dag);
    deg_inv_kernel<<<(N_net + 255) / 256, 256>>>(deg_net, N_net);
    deg_inv_kernel<<<(N_dag + 255) / 256, 256>>>(deg_dag, N_dag);

    // --- feature transform h = x @ W ---
    gemm128_kernel<<<(N_net + 63) / 64, 256, smem_gemm>>>(net_feat, W_net, h_net, N_net);
    gemm128_kernel<<<(N_dag + 63) / 64, 256, smem_gemm>>>(dag_feat, W_dag, h_dag, N_dag);

    // --- normalized edge scatter (one warp per edge) ---
    scatter_kernel<<<(E_net + 7) / 8, 256>>>(net_ei, net_ew, deg_net, h_net, agg_net, E_net);
    scatter_kernel<<<(E_dag + 7) / 8, 256>>>(dag_ei, dag_ew, deg_dag, h_dag, agg_dag, E_dag);

    // --- epilogue: self-loop + bias + relu + l2norm + mean accumulate ---
    epilogue_kernel<<<1184, 256>>>(agg_net, h_net, deg_net, b_net, acc, N_net);
    epilogue_kernel<<<1184, 256>>>(agg_dag, h_dag, deg_dag, b_dag, acc + D, N_dag);

    // --- final MLP -> scalar ---
    final_mlp_kernel<<<1, 256>>>(acc, W1, b1, W2, b2,
                                 1.0f / (float)N_net, 1.0f / (float)N_dag, out);
}

// round 2
// speedup vs baseline: 2.3890x; 2.3890x over previous
#include <cuda_runtime.h>

#define D 128
#define MAXN_NET 100000
#define MAXN_DAG 50000
#define MAXE_NET 600000
#define MAXE_DAG 400000

// ---------------- device scratch (allocation-free rule: __device__ globals) ---
__device__ __align__(16) float g_h_net[MAXN_NET * D];
__device__ __align__(16) float g_h_dag[MAXN_DAG * D];
__device__ float g_deg_net[MAXN_NET];      // deg -> dinv in place
__device__ float g_deg_dag[MAXN_DAG];
__device__ int   g_cnt_net[MAXN_NET];
__device__ int   g_cnt_dag[MAXN_DAG];
__device__ int   g_rs_net[MAXN_NET];       // CSR row starts
__device__ int   g_rs_dag[MAXN_DAG];
__device__ int   g_ptr_net[MAXN_NET];      // fill cursors
__device__ int   g_ptr_dag[MAXN_DAG];
__device__ int   g_esrc_net[MAXE_NET];
__device__ int   g_esrc_dag[MAXE_DAG];
__device__ float g_enorm_net[MAXE_NET];
__device__ float g_enorm_dag[MAXE_DAG];
__device__ int   g_bsum_net[32];
__device__ int   g_bsum_dag[32];
__device__ __align__(16) float g_acc[2 * D];   // [0:128) net mean-acc, [128:256) dag

// ---------------- f32x2 packed-FMA helpers ------------------------------------
typedef unsigned long long u64;

__device__ __forceinline__ u64 pk2(float lo, float hi) {
    u64 r;
    asm("mov.b64 %0, {%1, %2};" : "=l"(r) : "f"(lo), "f"(hi));
    return r;
}
__device__ __forceinline__ void upk2(u64 v, float& lo, float& hi) {
    asm("mov.b64 {%0, %1}, %2;" : "=f"(lo), "=f"(hi) : "l"(v));
}
__device__ __forceinline__ void ffma2(u64& d, u64 a, u64 b) {
    asm("fma.rn.f32x2 %0, %1, %2, %0;" : "+l"(d) : "l"(a), "l"(b));
}
__device__ __forceinline__ float f4get(const float4& v, int k) {
    switch (k) { case 0: return v.x; case 1: return v.y; case 2: return v.z; }
    return v.w;
}

// ---------------- tiny utility kernels ----------------------------------------
__global__ void zero_acc_kernel(float* acc) { acc[threadIdx.x] = 0.f; }

__global__ void init_kernel(float* deg, int* cnt, int n) {
    int i = blockIdx.x * blockDim.x + threadIdx.x;
    if (i < n) { deg[i] = 1.0f; cnt[i] = 0; }       // self-loop weight 1
}

__global__ void hist_kernel(const int* __restrict__ ei,
                            const float* __restrict__ ew,
                            float* __restrict__ deg,
                            int* __restrict__ cnt, int E) {
    int e = blockIdx.x * blockDim.x + threadIdx.x;
    if (e < E) {
        int dst = ei[E + e];
        atomicAdd(&deg[dst], ew[e]);
        atomicAdd(&cnt[dst], 1);
    }
}

// exclusive scan, 4096 elements per block (256 thr x 16)
__global__ void scan1_kernel(const int* __restrict__ cnt, int* __restrict__ rs,
                             int* __restrict__ bsum, int N) {
    int t = threadIdx.x;
    int base = blockIdx.x * 4096 + t * 16;
    int v[16], s = 0;
#pragma unroll
    for (int j = 0; j < 16; j++) {
        int idx = base + j;
        v[j] = (idx < N) ? cnt[idx] : 0;
        s += v[j];
    }
    int lane = t & 31, wid = t >> 5;
    int x = s;
#pragma unroll
    for (int o = 1; o < 32; o <<= 1) {
        int y = __shfl_up_sync(0xFFFFFFFFu, x, o);
        if (lane >= o) x += y;
    }
    __shared__ int wt[8];
    if (lane == 31) wt[wid] = x;
    __syncthreads();
    if (t < 8) {
        int y = wt[t];
#pragma unroll
        for (int o = 1; o < 8; o <<= 1) {
            int z = __shfl_up_sync(0xFFu, y, o);
            if (t >= o) y += z;
        }
        wt[t] = y;
    }
    __syncthreads();
    int excl = x - s + (wid ? wt[wid - 1] : 0);
    int run = excl;
#pragma unroll
    for (int j = 0; j < 16; j++) {
        int idx = base + j;
        if (idx < N) rs[idx] = run;
        run += v[j];
    }
    if (t == 255) bsum[blockIdx.x] = excl + s;
}

__global__ void scan2_kernel(int* bsum, int nb) {
    int t = threadIdx.x;                   // 32 threads
    int v = (t < nb) ? bsum[t] : 0;
    int x = v;
#pragma unroll
    for (int o = 1; o < 32; o <<= 1) {
        int y = __shfl_up_sync(0xFFFFFFFFu, x, o);
        if (t >= o) x += y;
    }
    if (t < nb) bsum[t] = x - v;           // exclusive
}

__global__ void scan3_kernel(int* __restrict__ rs, int* __restrict__ ptr,
                             float* __restrict__ deg,
                             const int* __restrict__ bsum, int N) {
    int i = blockIdx.x * blockDim.x + threadIdx.x;
    if (i < N) {
        int r = rs[i] + bsum[i >> 12];
        rs[i] = r;
        ptr[i] = r;
        deg[i] = rsqrtf(deg[i]);           // deg >= 1 (self-loop), becomes dinv
    }
}

__global__ void reorder_kernel(const int* __restrict__ ei,
                               const float* __restrict__ ew,
                               const float* __restrict__ dinv,
                               int* __restrict__ ptr,
                               int* __restrict__ esrc,
                               float* __restrict__ enorm, int E) {
    int e = blockIdx.x * blockDim.x + threadIdx.x;
    if (e < E) {
        int src = ei[e];
        int dst = ei[E + e];
        float nm = dinv[src] * ew[e] * dinv[dst];
        int p = atomicAdd(&ptr[dst], 1);
        esrc[p] = src;
        enorm[p] = nm;
    }
}

// ---------------- GEMM: H[N,128] = X[N,128] @ W[128,128] ----------------------
// 64-row tile, 256 thr, 8 rows x 4 cols per thread, packed f32x2 FMAs.
__global__ void __launch_bounds__(256, 2)
gemm128_kernel(const float* __restrict__ X, const float* __restrict__ W,
               float* __restrict__ H, int N) {
    extern __shared__ float sm[];
    float4* As4 = (float4*)sm;               // [64][32] float4
    float4* Bs4 = (float4*)(sm + 64 * D);    // [128][32] float4
    const int tid = threadIdx.x;
    const int row0 = blockIdx.x * 64;

    const float4* W4 = (const float4*)W;
#pragma unroll
    for (int i = 0; i < 16; i++) Bs4[tid + 256 * i] = W4[tid + 256 * i];

#pragma unroll
    for (int i = 0; i < 8; i++) {
        int idx = tid + 256 * i;
        int r = idx >> 5, c = idx & 31;
        int grow = row0 + r;
        float4 v = make_float4(0.f, 0.f, 0.f, 0.f);
        if (grow < N) v = ((const float4*)X)[grow * 32 + c];
        As4[idx] = v;
    }
    __syncthreads();

    const int tx = tid & 31;    // 4 output cols at tx*4
    const int ty = tid >> 5;    // 8 output rows at ty*8 (4 packed pairs)
    u64 acc2[4][4];
#pragma unroll
    for (int p = 0; p < 4; p++)
#pragma unroll
        for (int c = 0; c < 4; c++) acc2[p][c] = 0ull;

#pragma unroll 4
    for (int k4 = 0; k4 < 32; k4++) {
        float4 a[8];
#pragma unroll
        for (int r = 0; r < 8; r++) a[r] = As4[(ty * 8 + r) * 32 + k4];  // bcast
#pragma unroll
        for (int kk = 0; kk < 4; kk++) {
            float4 b = Bs4[(k4 * 4 + kk) * 32 + tx];
            u64 bx = pk2(b.x, b.x), by = pk2(b.y, b.y);
            u64 bz = pk2(b.z, b.z), bw = pk2(b.w, b.w);
#pragma unroll
            for (int p = 0; p < 4; p++) {
                u64 aa = pk2(f4get(a[2 * p], kk), f4get(a[2 * p + 1], kk));
                ffma2(acc2[p][0], aa, bx);
                ffma2(acc2[p][1], aa, by);
                ffma2(acc2[p][2], aa, bz);
                ffma2(acc2[p][3], aa, bw);
            }
        }
    }

#pragma unroll
    for (int p = 0; p < 4; p++) {
        float4 v0, v1;
        upk2(acc2[p][0], v0.x, v1.x);
        upk2(acc2[p][1], v0.y, v1.y);
        upk2(acc2[p][2], v0.z, v1.z);
        upk2(acc2[p][3], v0.w, v1.w);
        int r0 = row0 + ty * 8 + 2 * p;
        if (r0 < N)     ((float4*)(H + r0 * D))[tx] = v0;
        if (r0 + 1 < N) ((float4*)(H + (r0 + 1) * D))[tx] = v1;
    }
}

// ------- fused gather: CSR aggregate + self-loop + bias + relu + l2norm + mean
__global__ void gather_fused_kernel(const int* __restrict__ rs,
                                    const int* __restrict__ cnt,
                                    const int* __restrict__ esrc,
                                    const float* __restrict__ enorm,
                                    const float* __restrict__ H,
                                    const float* __restrict__ dinv,
                                    const float* __restrict__ b,
                                    float* __restrict__ acc_out, int N) {
    __shared__ float sacc[D];
    int t = threadIdx.x;
    if (t < D) sacc[t] = 0.f;
    __syncthreads();

    int lane = t & 31;
    int warp = (blockIdx.x * blockDim.x + t) >> 5;
    int nwarps = (gridDim.x * blockDim.x) >> 5;
    float4 bb = ((const float4*)b)[lane];
    float4 macc = make_float4(0.f, 0.f, 0.f, 0.f);

    for (int i = warp; i < N; i += nwarps) {
        float di = dinv[i];
        float dd = di * di;                                   // self-loop norm
        float4 v = ((const float4*)(H + (long)i * D))[lane];
        v.x *= dd; v.y *= dd; v.z *= dd; v.w *= dd;
        int s = rs[i];
        int c = cnt[i];
#pragma unroll 2
        for (int j = 0; j < c; j++) {
            int src = __ldg(&esrc[s + j]);                    // warp-broadcast
            float nm = __ldg(&enorm[s + j]);
            float4 hh = ((const float4*)(H + (long)src * D))[lane];
            v.x += nm * hh.x; v.y += nm * hh.y;
            v.z += nm * hh.z; v.w += nm * hh.w;
        }
        v.x = fmaxf(v.x + bb.x, 0.f);
        v.y = fmaxf(v.y + bb.y, 0.f);
        v.z = fmaxf(v.z + bb.z, 0.f);
        v.w = fmaxf(v.w + bb.w, 0.f);
        float ss = v.x * v.x + v.y * v.y + v.z * v.z + v.w * v.w;
#pragma unroll
        for (int o = 16; o; o >>= 1) ss += __shfl_xor_sync(0xFFFFFFFFu, ss, o);
        float scale = 1.0f / fmaxf(sqrtf(ss), 1e-12f);        // l2norm
        macc.x += v.x * scale;
        macc.y += v.y * scale;
        macc.z += v.z * scale;
        macc.w += v.w * scale;
    }
    float* so = sacc + lane * 4;
    atomicAdd(so + 0, macc.x);
    atomicAdd(so + 1, macc.y);
    atomicAdd(so + 2, macc.z);
    atomicAdd(so + 3, macc.w);
    __syncthreads();
    if (t < D) atomicAdd(acc_out + t, sacc[t]);
}

// ---------------- final MLP: concat means -> 64 relu -> 1 ---------------------
__global__ void final_mlp_kernel(const float* __restrict__ acc,
                                 const float* __restrict__ W1,
                                 const float* __restrict__ b1,
                                 const float* __restrict__ W2,
                                 const float* __restrict__ b2,
                                 float invNnet, float invNdag,
                                 float* __restrict__ out) {
    __shared__ float c[256];
    __shared__ float h1[64];
    int t = threadIdx.x;   // 256 threads
    c[t] = acc[t] * (t < 128 ? invNnet : invNdag);
    __syncthreads();
    if (t < 64) {
        float s = b1[t];
#pragma unroll 8
        for (int i = 0; i < 256; i++) s += c[i] * W1[i * 64 + t];
        h1[t] = fmaxf(s, 0.f);
    }
    __syncthreads();
    if (t == 0) {
        float s = b2[0];
#pragma unroll
        for (int j = 0; j < 64; j++) s += h1[j] * W2[j];
        out[0] = s;
    }
}

// ---------------- launch -------------------------------------------------------
extern "C" void kernel_launch(void* const* d_in, const int* in_sizes, int n_in,
                              void* d_out, int out_size) {
    const float* net_feat = (const float*)d_in[0];
    const int*   net_ei   = (const int*)  d_in[1];
    const float* net_ew   = (const float*)d_in[2];
    const float* dag_feat = (const float*)d_in[3];
    const int*   dag_ei   = (const int*)  d_in[4];
    const float* dag_ew   = (const float*)d_in[5];
    const float* W_net    = (const float*)d_in[6];
    const float* b_net    = (const float*)d_in[7];
    const float* W_dag    = (const float*)d_in[8];
    const float* b_dag    = (const float*)d_in[9];
    const float* W1       = (const float*)d_in[10];
    const float* b1       = (const float*)d_in[11];
    const float* W2       = (const float*)d_in[12];
    const float* b2       = (const float*)d_in[13];
    float* out = (float*)d_out;

    const int N_net = in_sizes[0] / D;
    const int E_net = in_sizes[2];
    const int N_dag = in_sizes[3] / D;
    const int E_dag = in_sizes[5];

    void *p;
    cudaGetSymbolAddress(&p, g_h_net);     float* h_net   = (float*)p;
    cudaGetSymbolAddress(&p, g_h_dag);     float* h_dag   = (float*)p;
    cudaGetSymbolAddress(&p, g_deg_net);   float* deg_net = (float*)p;
    cudaGetSymbolAddress(&p, g_deg_dag);   float* deg_dag = (float*)p;
    cudaGetSymbolAddress(&p, g_cnt_net);   int* cnt_net   = (int*)p;
    cudaGetSymbolAddress(&p, g_cnt_dag);   int* cnt_dag   = (int*)p;
    cudaGetSymbolAddress(&p, g_rs_net);    int* rs_net    = (int*)p;
    cudaGetSymbolAddress(&p, g_rs_dag);    int* rs_dag    = (int*)p;
    cudaGetSymbolAddress(&p, g_ptr_net);   int* ptr_net   = (int*)p;
    cudaGetSymbolAddress(&p, g_ptr_dag);   int* ptr_dag   = (int*)p;
    cudaGetSymbolAddress(&p, g_esrc_net);  int* esrc_net  = (int*)p;
    cudaGetSymbolAddress(&p, g_esrc_dag);  int* esrc_dag  = (int*)p;
    cudaGetSymbolAddress(&p, g_enorm_net); float* enorm_net = (float*)p;
    cudaGetSymbolAddress(&p, g_enorm_dag); float* enorm_dag = (float*)p;
    cudaGetSymbolAddress(&p, g_bsum_net);  int* bsum_net  = (int*)p;
    cudaGetSymbolAddress(&p, g_bsum_dag);  int* bsum_dag  = (int*)p;
    cudaGetSymbolAddress(&p, g_acc);       float* acc     = (float*)p;

    const int smem_gemm = (64 * D + D * D) * (int)sizeof(float);  // 96 KB
    cudaFuncSetAttribute(gemm128_kernel,
                         cudaFuncAttributeMaxDynamicSharedMemorySize, smem_gemm);

    const int nb_net = (N_net + 4095) / 4096;
    const int nb_dag = (N_dag + 4095) / 4096;

    zero_acc_kernel<<<1, 2 * D>>>(acc);

    // ---- CSR build: net ----
    init_kernel<<<(N_net + 255) / 256, 256>>>(deg_net, cnt_net, N_net);
    hist_kernel<<<(E_net + 255) / 256, 256>>>(net_ei, net_ew, deg_net, cnt_net, E_net);
    scan1_kernel<<<nb_net, 256>>>(cnt_net, rs_net, bsum_net, N_net);
    scan2_kernel<<<1, 32>>>(bsum_net, nb_net);
    scan3_kernel<<<(N_net + 255) / 256, 256>>>(rs_net, ptr_net, deg_net, bsum_net, N_net);
    reorder_kernel<<<(E_net + 255) / 256, 256>>>(net_ei, net_ew, deg_net, ptr_net,
                                                 esrc_net, enorm_net, E_net);
    // ---- CSR build: dag ----
    init_kernel<<<(N_dag + 255) / 256, 256>>>(deg_dag, cnt_dag, N_dag);
    hist_kernel<<<(E_dag + 255) / 256, 256>>>(dag_ei, dag_ew, deg_dag, cnt_dag, E_dag);
    scan1_kernel<<<nb_dag, 256>>>(cnt_dag, rs_dag, bsum_dag, N_dag);
    scan2_kernel<<<1, 32>>>(bsum_dag, nb_dag);
    scan3_kernel<<<(N_dag + 255) / 256, 256>>>(rs_dag, ptr_dag, deg_dag, bsum_dag, N_dag);
    reorder_kernel<<<(E_dag + 255) / 256, 256>>>(dag_ei, dag_ew, deg_dag, ptr_dag,
                                                 esrc_dag, enorm_dag, E_dag);

    // ---- feature transform h = x @ W ----
    gemm128_kernel<<<(N_net + 63) / 64, 256, smem_gemm>>>(net_feat, W_net, h_net, N_net);
    gemm128_kernel<<<(N_dag + 63) / 64, 256, smem_gemm>>>(dag_feat, W_dag, h_dag, N_dag);

    // ---- fused aggregate + epilogue -> mean accumulators ----
    gather_fused_kernel<<<1184, 256>>>(rs_net, cnt_net, esrc_net, enorm_net,
                                       h_net, deg_net, b_net, acc, N_net);
    gather_fused_kernel<<<1184, 256>>>(rs_dag, cnt_dag, esrc_dag, enorm_dag,
                                       h_dag, deg_dag, b_dag, acc + D, N_dag);

    // ---- final MLP -> scalar ----
    final_mlp_kernel<<<1, 256>>>(acc, W1, b1, W2, b2,
                                 1.0f / (float)N_net, 1.0f / (float)N_dag, out);
}

// round 3
// speedup vs baseline: 3.0527x; 1.2778x over previous
#include <cuda_runtime.h>
#include <cuda_bf16.h>

#define D 128
#define MAXN_NET 100000
#define MAXN_DAG 50000
#define MAXE_NET 600000
#define MAXE_DAG 400000

// ---------------- device scratch (allocation-free rule: __device__ globals) ---
__device__ __align__(16) __nv_bfloat16 g_h_net[MAXN_NET * D];
__device__ __align__(16) __nv_bfloat16 g_h_dag[MAXN_DAG * D];
__device__ float g_deg_net[MAXN_NET];
__device__ float g_deg_dag[MAXN_DAG];
__device__ int   g_cnt_net[MAXN_NET];
__device__ int   g_cnt_dag[MAXN_DAG];
__device__ int   g_rs_net[MAXN_NET];
__device__ int   g_rs_dag[MAXN_DAG];
__device__ int   g_ptr_net[MAXN_NET];
__device__ int   g_ptr_dag[MAXN_DAG];
__device__ __align__(16) int2 g_ed_net[MAXE_NET];   // (src, norm-as-int)
__device__ __align__(16) int2 g_ed_dag[MAXE_DAG];
__device__ int   g_bsum_net[32];
__device__ int   g_bsum_dag[32];
__device__ __align__(16) float g_acc[2 * D];

// ---------------- helpers ------------------------------------------------------
typedef unsigned long long u64;

__device__ __forceinline__ u64 pk2(float lo, float hi) {
    u64 r;
    asm("mov.b64 %0, {%1, %2};" : "=l"(r) : "f"(lo), "f"(hi));
    return r;
}
__device__ __forceinline__ void upk2(u64 v, float& lo, float& hi) {
    asm("mov.b64 {%0, %1}, %2;" : "=f"(lo), "=f"(hi) : "l"(v));
}
__device__ __forceinline__ void ffma2(u64& d, u64 a, u64 b) {
    asm("fma.rn.f32x2 %0, %1, %2, %0;" : "+l"(d) : "l"(a), "l"(b));
}
__device__ __forceinline__ float f4get(const float4& v, int k) {
    switch (k) { case 0: return v.x; case 1: return v.y; case 2: return v.z; }
    return v.w;
}
__device__ __forceinline__ uint2 f4_to_bf16x4(float4 v) {
    __nv_bfloat162 p0 = __float22bfloat162_rn(make_float2(v.x, v.y));
    __nv_bfloat162 p1 = __float22bfloat162_rn(make_float2(v.z, v.w));
    return make_uint2(*reinterpret_cast<unsigned*>(&p0),
                      *reinterpret_cast<unsigned*>(&p1));
}
__device__ __forceinline__ float4 bf16x4_to_f4(uint2 u) {
    __nv_bfloat162 p0 = *reinterpret_cast<__nv_bfloat162*>(&u.x);
    __nv_bfloat162 p1 = *reinterpret_cast<__nv_bfloat162*>(&u.y);
    float2 f0 = __bfloat1622float2(p0);
    float2 f1 = __bfloat1622float2(p1);
    return make_float4(f0.x, f0.y, f1.x, f1.y);
}

// ---------------- GEMM body: H[N,128] = X[N,128] @ W[128,128], bf16 out -------
__device__ void gemm_body(const float* __restrict__ X, const float* __restrict__ W,
                          __nv_bfloat16* __restrict__ Hb, int N, int bid) {
    extern __shared__ float sm[];
    float4* As4 = (float4*)sm;               // [64][32] float4
    float4* Bs4 = (float4*)(sm + 64 * D);    // [128][32] float4
    const int tid = threadIdx.x;
    const int row0 = bid * 64;

    const float4* W4 = (const float4*)W;
#pragma unroll
    for (int i = 0; i < 16; i++) Bs4[tid + 256 * i] = W4[tid + 256 * i];

#pragma unroll
    for (int i = 0; i < 8; i++) {
        int idx = tid + 256 * i;
        int r = idx >> 5, c = idx & 31;
        int grow = row0 + r;
        float4 v = make_float4(0.f, 0.f, 0.f, 0.f);
        if (grow < N) v = ((const float4*)X)[grow * 32 + c];
        As4[idx] = v;
    }
    __syncthreads();

    const int tx = tid & 31;
    const int ty = tid >> 5;
    u64 acc2[4][4];
#pragma unroll
    for (int p = 0; p < 4; p++)
#pragma unroll
        for (int c = 0; c < 4; c++) acc2[p][c] = 0ull;

#pragma unroll 4
    for (int k4 = 0; k4 < 32; k4++) {
        float4 a[8];
#pragma unroll
        for (int r = 0; r < 8; r++) a[r] = As4[(ty * 8 + r) * 32 + k4];
#pragma unroll
        for (int kk = 0; kk < 4; kk++) {
            float4 b = Bs4[(k4 * 4 + kk) * 32 + tx];
            u64 bx = pk2(b.x, b.x), by = pk2(b.y, b.y);
            u64 bz = pk2(b.z, b.z), bw = pk2(b.w, b.w);
#pragma unroll
            for (int p = 0; p < 4; p++) {
                u64 aa = pk2(f4get(a[2 * p], kk), f4get(a[2 * p + 1], kk));
                ffma2(acc2[p][0], aa, bx);
                ffma2(acc2[p][1], aa, by);
                ffma2(acc2[p][2], aa, bz);
                ffma2(acc2[p][3], aa, bw);
            }
        }
    }

#pragma unroll
    for (int p = 0; p < 4; p++) {
        float4 v0, v1;
        upk2(acc2[p][0], v0.x, v1.x);
        upk2(acc2[p][1], v0.y, v1.y);
        upk2(acc2[p][2], v0.z, v1.z);
        upk2(acc2[p][3], v0.w, v1.w);
        int r0 = row0 + ty * 8 + 2 * p;
        if (r0 < N)     ((uint2*)(Hb + (size_t)r0 * D))[tx] = f4_to_bf16x4(v0);
        if (r0 + 1 < N) ((uint2*)(Hb + (size_t)(r0 + 1) * D))[tx] = f4_to_bf16x4(v1);
    }
}

// ---------------- K0: init deg/cnt both graphs + zero acc ----------------------
__global__ void init_kernel(float* deg_n, int* cnt_n, int Nn,
                            float* deg_d, int* cnt_d, int Nd,
                            float* acc) {
    int i = blockIdx.x * blockDim.x + threadIdx.x;
    int stride = gridDim.x * blockDim.x;
    for (; i < Nn; i += stride) {
        deg_n[i] = 1.0f; cnt_n[i] = 0;                    // self-loop weight 1
        if (i < Nd) { deg_d[i] = 1.0f; cnt_d[i] = 0; }
        if (i < 2 * D) acc[i] = 0.f;
    }
}

// ---------------- K1: hist(both) + GEMM(net) -----------------------------------
__global__ void __launch_bounds__(256, 2)
k_hist_gemmnet(const int* __restrict__ ei_n, const float* __restrict__ ew_n,
               float* __restrict__ deg_n, int* __restrict__ cnt_n, int En,
               const int* __restrict__ ei_d, const float* __restrict__ ew_d,
               float* __restrict__ deg_d, int* __restrict__ cnt_d, int Ed,
               int histBlocks,
               const float* __restrict__ X, const float* __restrict__ W,
               __nv_bfloat16* __restrict__ Hb, int N) {
    if ((int)blockIdx.x < histBlocks) {
        int stride = histBlocks * 256;
        int total = En + Ed;
        for (int i = blockIdx.x * 256 + threadIdx.x; i < total; i += stride) {
            if (i < En) {
                int dst = ei_n[En + i];
                atomicAdd(&deg_n[dst], ew_n[i]);
                atomicAdd(&cnt_n[dst], 1);
            } else {
                int e = i - En;
                int dst = ei_d[Ed + e];
                atomicAdd(&deg_d[dst], ew_d[e]);
                atomicAdd(&cnt_d[dst], 1);
            }
        }
    } else {
        gemm_body(X, W, Hb, N, blockIdx.x - histBlocks);
    }
}

// ---------------- scan chain (both graphs per launch) ---------------------------
__global__ void scan1_kernel(const int* __restrict__ cnt_n, int* __restrict__ rs_n,
                             int* __restrict__ bs_n, int Nn, int nbN,
                             const int* __restrict__ cnt_d, int* __restrict__ rs_d,
                             int* __restrict__ bs_d, int Nd) {
    const int* cnt; int* rs; int* bsum; int N; int blk;
    if ((int)blockIdx.x < nbN) { cnt = cnt_n; rs = rs_n; bsum = bs_n; N = Nn; blk = blockIdx.x; }
    else { cnt = cnt_d; rs = rs_d; bsum = bs_d; N = Nd; blk = blockIdx.x - nbN; }

    int t = threadIdx.x;
    int base = blk * 4096 + t * 16;
    int v[16], s = 0;
#pragma unroll
    for (int j = 0; j < 16; j++) {
        int idx = base + j;
        v[j] = (idx < N) ? cnt[idx] : 0;
        s += v[j];
    }
    int lane = t & 31, wid = t >> 5;
    int x = s;
#pragma unroll
    for (int o = 1; o < 32; o <<= 1) {
        int y = __shfl_up_sync(0xFFFFFFFFu, x, o);
        if (lane >= o) x += y;
    }
    __shared__ int wt[8];
    if (lane == 31) wt[wid] = x;
    __syncthreads();
    if (t < 8) {
        int y = wt[t];
#pragma unroll
        for (int o = 1; o < 8; o <<= 1) {
            int z = __shfl_up_sync(0xFFu, y, o);
            if (t >= o) y += z;
        }
        wt[t] = y;
    }
    __syncthreads();
    int excl = x - s + (wid ? wt[wid - 1] : 0);
    int run = excl;
#pragma unroll
    for (int j = 0; j < 16; j++) {
        int idx = base + j;
        if (idx < N) rs[idx] = run;
        run += v[j];
    }
    if (t == 255) bsum[blk] = excl + s;
}

__global__ void scan2_kernel(int* bs_n, int nbN, int* bs_d, int nbD) {
    int* bsum = blockIdx.x ? bs_d : bs_n;
    int nb = blockIdx.x ? nbD : nbN;
    int t = threadIdx.x;
    int v = (t < nb) ? bsum[t] : 0;
    int x = v;
#pragma unroll
    for (int o = 1; o < 32; o <<= 1) {
        int y = __shfl_up_sync(0xFFFFFFFFu, x, o);
        if (t >= o) x += y;
    }
    if (t < nb) bsum[t] = x - v;
}

__global__ void scan3_kernel(int* __restrict__ rs_n, int* __restrict__ ptr_n,
                             const int* __restrict__ bs_n, int Nn, int nb3N,
                             int* __restrict__ rs_d, int* __restrict__ ptr_d,
                             const int* __restrict__ bs_d, int Nd) {
    int* rs; int* ptr; const int* bsum; int N; int i;
    if ((int)blockIdx.x < nb3N) {
        rs = rs_n; ptr = ptr_n; bsum = bs_n; N = Nn;
        i = blockIdx.x * 256 + threadIdx.x;
    } else {
        rs = rs_d; ptr = ptr_d; bsum = bs_d; N = Nd;
        i = (blockIdx.x - nb3N) * 256 + threadIdx.x;
    }
    if (i < N) {
        int r = rs[i] + bsum[i >> 12];
        rs[i] = r;
        ptr[i] = r;
    }
}

// ---------------- K3: reorder(both) + GEMM(dag) ---------------------------------
__global__ void __launch_bounds__(256, 2)
k_reorder_gemmdag(const int* __restrict__ ei_n, const float* __restrict__ ew_n,
                  const float* __restrict__ deg_n, int* __restrict__ ptr_n,
                  int2* __restrict__ ed_n, int En,
                  const int* __restrict__ ei_d, const float* __restrict__ ew_d,
                  const float* __restrict__ deg_d, int* __restrict__ ptr_d,
                  int2* __restrict__ ed_d, int Ed,
                  int reorderBlocks,
                  const float* __restrict__ X, const float* __restrict__ W,
                  __nv_bfloat16* __restrict__ Hb, int N) {
    if ((int)blockIdx.x < reorderBlocks) {
        int stride = reorderBlocks * 256;
        int total = En + Ed;
        for (int i = blockIdx.x * 256 + threadIdx.x; i < total; i += stride) {
            const int* ei; const float* ew; const float* deg; int* ptr;
            int2* ed; int E, e;
            if (i < En) { ei = ei_n; ew = ew_n; deg = deg_n; ptr = ptr_n; ed = ed_n; E = En; e = i; }
            else        { ei = ei_d; ew = ew_d; deg = deg_d; ptr = ptr_d; ed = ed_d; E = Ed; e = i - En; }
            int src = ei[e];
            int dst = ei[E + e];
            float nm = rsqrtf(deg[src]) * ew[e] * rsqrtf(deg[dst]);
            int p = atomicAdd(&ptr[dst], 1);
            ed[p] = make_int2(src, __float_as_int(nm));
        }
    } else {
        gemm_body(X, W, Hb, N, blockIdx.x - reorderBlocks);
    }
}

// ---------------- K4: fused gather + epilogue, both graphs ----------------------
__global__ void gather_kernel(const int* __restrict__ rs_n, const int* __restrict__ cnt_n,
                              const int2* __restrict__ ed_n,
                              const __nv_bfloat16* __restrict__ Hn,
                              const float* __restrict__ deg_n,
                              const float* __restrict__ b_n, int Nn, int blocksNet,
                              const int* __restrict__ rs_d, const int* __restrict__ cnt_d,
                              const int2* __restrict__ ed_d,
                              const __nv_bfloat16* __restrict__ Hd,
                              const float* __restrict__ deg_d,
                              const float* __restrict__ b_d,  int Nd,
                              float* __restrict__ acc) {
    bool isNet = (int)blockIdx.x < blocksNet;
    const int* rs   = isNet ? rs_n  : rs_d;
    const int* cnt  = isNet ? cnt_n : cnt_d;
    const int2* ed  = isNet ? ed_n  : ed_d;
    const __nv_bfloat16* H = isNet ? Hn : Hd;
    const float* deg = isNet ? deg_n : deg_d;
    const float* bia = isNet ? b_n : b_d;
    int N = isNet ? Nn : Nd;
    float* accBase = isNet ? acc : acc + D;
    int blk  = isNet ? blockIdx.x : blockIdx.x - blocksNet;
    int nblk = isNet ? blocksNet : gridDim.x - blocksNet;

    __shared__ float sacc[D];
    int t = threadIdx.x;
    if (t < D) sacc[t] = 0.f;
    __syncthreads();

    int lane = t & 31;
    int warp = blk * 8 + (t >> 5);
    int nwarps = nblk * 8;
    float4 bb = ((const float4*)bia)[lane];
    float4 macc = make_float4(0.f, 0.f, 0.f, 0.f);

    for (int i = warp; i < N; i += nwarps) {
        float dd = 1.0f / deg[i];                      // = dinv^2 (self-loop)
        float4 v = bf16x4_to_f4(((const uint2*)(H + (size_t)i * D))[lane]);
        v.x *= dd; v.y *= dd; v.z *= dd; v.w *= dd;
        int s = rs[i];
        int c = cnt[i];
#pragma unroll 2
        for (int j = 0; j < c; j++) {
            int2 e = __ldg(&ed[s + j]);                // warp-broadcast
            int src = e.x;
            float nm = __int_as_float(e.y);
            float4 hh = bf16x4_to_f4(((const uint2*)(H + (size_t)src * D))[lane]);
            v.x += nm * hh.x; v.y += nm * hh.y;
            v.z += nm * hh.z; v.w += nm * hh.w;
        }
        v.x = fmaxf(v.x + bb.x, 0.f);
        v.y = fmaxf(v.y + bb.y, 0.f);
        v.z = fmaxf(v.z + bb.z, 0.f);
        v.w = fmaxf(v.w + bb.w, 0.f);
        float ss = v.x * v.x + v.y * v.y + v.z * v.z + v.w * v.w;
#pragma unroll
        for (int o = 16; o; o >>= 1) ss += __shfl_xor_sync(0xFFFFFFFFu, ss, o);
        float scale = 1.0f / fmaxf(sqrtf(ss), 1e-12f);
        macc.x += v.x * scale;
        macc.y += v.y * scale;
        macc.z += v.z * scale;
        macc.w += v.w * scale;
    }
    float* so = sacc + lane * 4;
    atomicAdd(so + 0, macc.x);
    atomicAdd(so + 1, macc.y);
    atomicAdd(so + 2, macc.z);
    atomicAdd(so + 3, macc.w);
    __syncthreads();
    if (t < D) atomicAdd(accBase + t, sacc[t]);
}

// ---------------- K5: final MLP --------------------------------------------------
__global__ void final_mlp_kernel(const float* __restrict__ acc,
                                 const float* __restrict__ W1,
                                 const float* __restrict__ b1,
                                 const float* __restrict__ W2,
                                 const float* __restrict__ b2,
                                 float invNnet, float invNdag,
                                 float* __restrict__ out) {
    __shared__ float c[256];
    __shared__ float h1[64];
    int t = threadIdx.x;   // 256 threads
    c[t] = acc[t] * (t < 128 ? invNnet : invNdag);
    __syncthreads();
    if (t < 64) {
        float s = b1[t];
#pragma unroll 8
        for (int i = 0; i < 256; i++) s += c[i] * W1[i * 64 + t];
        h1[t] = fmaxf(s, 0.f);
    }
    __syncthreads();
    if (t == 0) {
        float s = b2[0];
#pragma unroll
        for (int j = 0; j < 64; j++) s += h1[j] * W2[j];
        out[0] = s;
    }
}

// ---------------- launch ----------------------------------------------------------
extern "C" void kernel_launch(void* const* d_in, const int* in_sizes, int n_in,
                              void* d_out, int out_size) {
    const float* net_feat = (const float*)d_in[0];
    const int*   net_ei   = (const int*)  d_in[1];
    const float* net_ew   = (const float*)d_in[2];
    const float* dag_feat = (const float*)d_in[3];
    const int*   dag_ei   = (const int*)  d_in[4];
    const float* dag_ew   = (const float*)d_in[5];
    const float* W_net    = (const float*)d_in[6];
    const float* b_net    = (const float*)d_in[7];
    const float* W_dag    = (const float*)d_in[8];
    const float* b_dag    = (const float*)d_in[9];
    const float* W1       = (const float*)d_in[10];
    const float* b1       = (const float*)d_in[11];
    const float* W2       = (const float*)d_in[12];
    const float* b2       = (const float*)d_in[13];
    float* out = (float*)d_out;

    const int N_net = in_sizes[0] / D;
    const int E_net = in_sizes[2];
    const int N_dag = in_sizes[3] / D;
    const int E_dag = in_sizes[5];

    void *p;
    cudaGetSymbolAddress(&p, g_h_net);   __nv_bfloat16* h_net = (__nv_bfloat16*)p;
    cudaGetSymbolAddress(&p, g_h_dag);   __nv_bfloat16* h_dag = (__nv_bfloat16*)p;
    cudaGetSymbolAddress(&p, g_deg_net); float* deg_net = (float*)p;
    cudaGetSymbolAddress(&p, g_deg_dag); float* deg_dag = (float*)p;
    cudaGetSymbolAddress(&p, g_cnt_net); int* cnt_net = (int*)p;
    cudaGetSymbolAddress(&p, g_cnt_dag); int* cnt_dag = (int*)p;
    cudaGetSymbolAddress(&p, g_rs_net);  int* rs_net = (int*)p;
    cudaGetSymbolAddress(&p, g_rs_dag);  int* rs_dag = (int*)p;
    cudaGetSymbolAddress(&p, g_ptr_net); int* ptr_net = (int*)p;
    cudaGetSymbolAddress(&p, g_ptr_dag); int* ptr_dag = (int*)p;
    cudaGetSymbolAddress(&p, g_ed_net);  int2* ed_net = (int2*)p;
    cudaGetSymbolAddress(&p, g_ed_dag);  int2* ed_dag = (int2*)p;
    cudaGetSymbolAddress(&p, g_bsum_net); int* bsum_net = (int*)p;
    cudaGetSymbolAddress(&p, g_bsum_dag); int* bsum_dag = (int*)p;
    cudaGetSymbolAddress(&p, g_acc);     float* acc = (float*)p;

    const int smem_gemm = (64 * D + D * D) * (int)sizeof(float);  // 96 KB
    cudaFuncSetAttribute(k_hist_gemmnet,
                         cudaFuncAttributeMaxDynamicSharedMemorySize, smem_gemm);
    cudaFuncSetAttribute(k_reorder_gemmdag,
                         cudaFuncAttributeMaxDynamicSharedMemorySize, smem_gemm);

    const int nb_net = (N_net + 4095) / 4096;
    const int nb_dag = (N_dag + 4095) / 4096;
    const int nb3N = (N_net + 255) / 256;
    const int nb3D = (N_dag + 255) / 256;

    // K0: init
    init_kernel<<<128, 256>>>(deg_net, cnt_net, N_net, deg_dag, cnt_dag, N_dag, acc);

    // K1: histogram(both) + GEMM(net)
    const int histBlocks = 256;
    k_hist_gemmnet<<<histBlocks + (N_net + 63) / 64, 256, smem_gemm>>>(
        net_ei, net_ew, deg_net, cnt_net, E_net,
        dag_ei, dag_ew, deg_dag, cnt_dag, E_dag,
        histBlocks, net_feat, W_net, h_net, N_net);

    // K2: scan chain (both graphs each launch)
    scan1_kernel<<<nb_net + nb_dag, 256>>>(cnt_net, rs_net, bsum_net, N_net, nb_net,
                                           cnt_dag, rs_dag, bsum_dag, N_dag);
    scan2_kernel<<<2, 32>>>(bsum_net, nb_net, bsum_dag, nb_dag);
    scan3_kernel<<<nb3N + nb3D, 256>>>(rs_net, ptr_net, bsum_net, N_net, nb3N,
                                       rs_dag, ptr_dag, bsum_dag, N_dag);

    // K3: reorder(both) + GEMM(dag)
    const int reorderBlocks = 192;
    k_reorder_gemmdag<<<reorderBlocks + (N_dag + 63) / 64, 256, smem_gemm>>>(
        net_ei, net_ew, deg_net, ptr_net, ed_net, E_net,
        dag_ei, dag_ew, deg_dag, ptr_dag, ed_dag, E_dag,
        reorderBlocks, dag_feat, W_dag, h_dag, N_dag);

    // K4: fused gather + epilogue (both graphs)
    const int blocksNet = 788, blocksDag = 396;
    gather_kernel<<<blocksNet + blocksDag, 256>>>(
        rs_net, cnt_net, ed_net, h_net, deg_net, b_net, N_net, blocksNet,
        rs_dag, cnt_dag, ed_dag, h_dag, deg_dag, b_dag, N_dag, acc);

    // K5: final MLP
    final_mlp_kernel<<<1, 256>>>(acc, W1, b1, W2, b2,
                                 1.0f / (float)N_net, 1.0f / (float)N_dag, out);
}

// round 5
// speedup vs baseline: 3.3678x; 1.1032x over previous
#include <cuda_runtime.h>
#include <cuda_bf16.h>

#define D 128
#define MAXN_NET 100000
#define MAXN_DAG 50000
#define MAXE_NET 600000
#define MAXE_DAG 400000

typedef unsigned long long u64;
typedef unsigned int u32;

// ---------------- device scratch (allocation-free rule: __device__ globals) ---
__device__ __align__(16) __nv_bfloat16 g_h_net[MAXN_NET * D];
__device__ __align__(16) __nv_bfloat16 g_h_dag[MAXN_DAG * D];
__device__ float g_deg_net[MAXN_NET];
__device__ float g_deg_dag[MAXN_DAG];
__device__ int   g_cnt_net[MAXN_NET];
__device__ int   g_cnt_dag[MAXN_DAG];
__device__ int   g_rs_net[MAXN_NET];
__device__ int   g_rs_dag[MAXN_DAG];
__device__ int   g_ptr_net[MAXN_NET];
__device__ int   g_ptr_dag[MAXN_DAG];
__device__ __align__(16) int2 g_ed_net[MAXE_NET];   // (src, norm-as-int)
__device__ __align__(16) int2 g_ed_dag[MAXE_DAG];
__device__ u64   g_status_net[64];                  // lookback: (value<<32)|flag
__device__ u64   g_status_dag[64];
__device__ int   g_done;
__device__ __align__(16) float g_acc[2 * D];

// ---------------- helpers ------------------------------------------------------
__device__ __forceinline__ u32 pack_bf16x2(float lo, float hi) {
    __nv_bfloat162 p = __float22bfloat162_rn(make_float2(lo, hi));
    return *reinterpret_cast<u32*>(&p);
}
__device__ __forceinline__ float4 bf16x4_to_f4(uint2 u) {
    __nv_bfloat162 p0 = *reinterpret_cast<__nv_bfloat162*>(&u.x);
    __nv_bfloat162 p1 = *reinterpret_cast<__nv_bfloat162*>(&u.y);
    float2 f0 = __bfloat1622float2(p0);
    float2 f1 = __bfloat1622float2(p1);
    return make_float4(f0.x, f0.y, f1.x, f1.y);
}
__device__ __forceinline__ u32 f2tf32(float f) {
    u32 r;
    asm("cvt.rna.tf32.f32 %0, %1;" : "=r"(r) : "f"(f));
    return r;
}
__device__ __forceinline__ uint4 f4_to_tf32x4(float4 v) {
    return make_uint4(f2tf32(v.x), f2tf32(v.y), f2tf32(v.z), f2tf32(v.w));
}
__device__ __forceinline__ void ldsm_x4(u32& r0, u32& r1, u32& r2, u32& r3, u32 a) {
    asm volatile("ldmatrix.sync.aligned.m8n8.x4.shared.b16 {%0,%1,%2,%3}, [%4];"
                 : "=r"(r0), "=r"(r1), "=r"(r2), "=r"(r3) : "r"(a));
}
__device__ __forceinline__ void mma_tf32(float c[4], u32 a0, u32 a1, u32 a2, u32 a3,
                                         u32 b0, u32 b1) {
    asm volatile(
        "mma.sync.aligned.m16n8k8.row.col.f32.tf32.tf32.f32 "
        "{%0,%1,%2,%3}, {%4,%5,%6,%7}, {%8,%9}, {%0,%1,%2,%3};"
        : "+f"(c[0]), "+f"(c[1]), "+f"(c[2]), "+f"(c[3])
        : "r"(a0), "r"(a1), "r"(a2), "r"(a3), "r"(b0), "r"(b1));
}

// ---------------- TF32 tensor-core GEMM body -----------------------------------
// H[N,128] = X[N,128] @ W[128,128]; block = 128 rows, 256 thr (8 warps 4x2).
// SMEM: A 128x128 tf32 (64KB) + Wt 128x128 tf32 transposed (64KB), XOR swizzle.
__device__ void gemm_body(const float* __restrict__ X, const float* __restrict__ W,
                          __nv_bfloat16* __restrict__ Hb, int N, int bid) {
    extern __shared__ char smem[];
    char* sA = smem;                 // row r: 128 floats (512B), chunk = 16B
    char* sB = smem + 64 * 1024;     // row n: 128 k-floats (512B)
    const int tid = threadIdx.x;
    const int row0 = bid * 128;

    // fill Wt (transpose W[k][n] -> sB[n][k]), coalesced over n
#pragma unroll
    for (int i = 0; i < 16; i++) {
        int idx = i * 256 + tid;
        int n = idx & 127, kc = idx >> 7;          // kc = k-chunk (4 floats)
        uint4 v = make_uint4(f2tf32(W[(kc * 4 + 0) * D + n]),
                             f2tf32(W[(kc * 4 + 1) * D + n]),
                             f2tf32(W[(kc * 4 + 2) * D + n]),
                             f2tf32(W[(kc * 4 + 3) * D + n]));
        *(uint4*)(sB + n * 512 + ((kc ^ (n & 7)) << 4)) = v;
    }
    // fill A (X rows, zero-pad past N)
#pragma unroll
    for (int i = 0; i < 16; i++) {
        int idx = i * 256 + tid;
        int r = idx >> 5, ch = idx & 31;
        int grow = row0 + r;
        float4 f = make_float4(0.f, 0.f, 0.f, 0.f);
        if (grow < N) f = ((const float4*)X)[grow * 32 + ch];
        *(uint4*)(sA + r * 512 + ((ch ^ (r & 7)) << 4)) = f4_to_tf32x4(f);
    }
    __syncthreads();

    const int lane = tid & 31;
    const int w = tid >> 5;
    const int m0 = (w >> 1) * 32;     // 4 warp-rows x 32
    const int n0 = (w & 1) * 64;      // 2 warp-cols x 64
    const int sub = lane >> 3, rowin = lane & 7;

    float c[2][8][4];
#pragma unroll
    for (int mt = 0; mt < 2; mt++)
#pragma unroll
        for (int nt = 0; nt < 8; nt++)
#pragma unroll
            for (int k = 0; k < 4; k++) c[mt][nt][k] = 0.f;

#pragma unroll
    for (int ks = 0; ks < 16; ks++) {              // k = ks*8 .. ks*8+7
        u32 a[2][4];
#pragma unroll
        for (int mt = 0; mt < 2; mt++) {
            int r = m0 + mt * 16 + (sub & 1) * 8 + rowin;
            int ch = ks * 2 + (sub >> 1);
            u32 addr = (u32)__cvta_generic_to_shared(
                sA + r * 512 + ((ch ^ (r & 7)) << 4));
            ldsm_x4(a[mt][0], a[mt][1], a[mt][2], a[mt][3], addr);
        }
        u32 b[4][4];                               // q covers 2 n-tiles each
#pragma unroll
        for (int q = 0; q < 4; q++) {
            int n = n0 + q * 16 + (sub >> 1) * 8 + rowin;
            int ch = ks * 2 + (sub & 1);
            u32 addr = (u32)__cvta_generic_to_shared(
                sB + n * 512 + ((ch ^ (n & 7)) << 4));
            ldsm_x4(b[q][0], b[q][1], b[q][2], b[q][3], addr);
        }
#pragma unroll
        for (int mt = 0; mt < 2; mt++)
#pragma unroll
            for (int nt = 0; nt < 8; nt++)
                mma_tf32(c[mt][nt], a[mt][0], a[mt][1], a[mt][2], a[mt][3],
                         b[nt >> 1][(nt & 1) * 2], b[nt >> 1][(nt & 1) * 2 + 1]);
    }

    // epilogue: fp32 acc -> bf16 store (guarded)
#pragma unroll
    for (int mt = 0; mt < 2; mt++)
#pragma unroll
        for (int nt = 0; nt < 8; nt++) {
            int r = m0 + mt * 16 + (lane >> 2);
            int col = n0 + nt * 8 + (lane & 3) * 2;
            int g0 = row0 + r, g1 = g0 + 8;
            if (g0 < N)
                *(u32*)(Hb + (size_t)g0 * D + col) = pack_bf16x2(c[mt][nt][0], c[mt][nt][1]);
            if (g1 < N)
                *(u32*)(Hb + (size_t)g1 * D + col) = pack_bf16x2(c[mt][nt][2], c[mt][nt][3]);
        }
}

// ---------------- K0: init -----------------------------------------------------
__global__ void init_kernel(float* deg_n, int* cnt_n, int Nn,
                            float* deg_d, int* cnt_d, int Nd,
                            u64* st_n, u64* st_d, float* acc, int* done) {
    int i = blockIdx.x * blockDim.x + threadIdx.x;
    int stride = gridDim.x * blockDim.x;
    for (; i < Nn; i += stride) {
        deg_n[i] = 1.0f; cnt_n[i] = 0;                    // self-loop weight 1
        if (i < Nd) { deg_d[i] = 1.0f; cnt_d[i] = 0; }
        if (i < 64) { st_n[i] = 0ull; st_d[i] = 0ull; }
        if (i < 2 * D) acc[i] = 0.f;
        if (i == 0) *done = 0;
    }
}

// ---------------- K1: hist(both) + GEMM(net) -----------------------------------
__global__ void __launch_bounds__(256, 1)
k_hist_gemmnet(const int* __restrict__ ei_n, const float* __restrict__ ew_n,
               float* __restrict__ deg_n, int* __restrict__ cnt_n, int En,
               const int* __restrict__ ei_d, const float* __restrict__ ew_d,
               float* __restrict__ deg_d, int* __restrict__ cnt_d, int Ed,
               int histBlocks,
               const float* __restrict__ X, const float* __restrict__ W,
               __nv_bfloat16* __restrict__ Hb, int N) {
    if ((int)blockIdx.x < histBlocks) {
        int stride = histBlocks * 256;
        int total = En + Ed;
        for (int i = blockIdx.x * 256 + threadIdx.x; i < total; i += stride) {
            if (i < En) {
                int dst = ei_n[En + i];
                atomicAdd(&deg_n[dst], ew_n[i]);
                atomicAdd(&cnt_n[dst], 1);
            } else {
                int e = i - En;
                int dst = ei_d[Ed + e];
                atomicAdd(&deg_d[dst], ew_d[e]);
                atomicAdd(&cnt_d[dst], 1);
            }
        }
    } else {
        gemm_body(X, W, Hb, N, blockIdx.x - histBlocks);
    }
}

// ---------------- K2: single-pass scan, decoupled lookback, both graphs --------
__global__ void scan_kernel(const int* __restrict__ cnt_n, int* __restrict__ rs_n,
                            int* __restrict__ ptr_n, int Nn, int nbN,
                            const int* __restrict__ cnt_d, int* __restrict__ rs_d,
                            int* __restrict__ ptr_d, int Nd,
                            u64* st_n, u64* st_d) {
    const int* cnt; int* rs; int* ptr; int N, blk;
    volatile u64* st;
    if ((int)blockIdx.x < nbN) {
        cnt = cnt_n; rs = rs_n; ptr = ptr_n; N = Nn; blk = blockIdx.x;
        st = (volatile u64*)st_n;
    } else {
        cnt = cnt_d; rs = rs_d; ptr = ptr_d; N = Nd; blk = blockIdx.x - nbN;
        st = (volatile u64*)st_d;
    }

    int t = threadIdx.x;
    int base = blk * 4096 + t * 16;
    int v[16], s = 0;
#pragma unroll
    for (int j = 0; j < 16; j++) {
        int idx = base + j;
        v[j] = (idx < N) ? cnt[idx] : 0;
        s += v[j];
    }
    int lane = t & 31, wid = t >> 5;
    int x = s;
#pragma unroll
    for (int o = 1; o < 32; o <<= 1) {
        int y = __shfl_up_sync(0xFFFFFFFFu, x, o);
        if (lane >= o) x += y;
    }
    __shared__ int wt[8];
    __shared__ int sprefix;
    if (lane == 31) wt[wid] = x;
    __syncthreads();
    if (t < 8) {
        int y = wt[t];
#pragma unroll
        for (int o = 1; o < 8; o <<= 1) {
            int z = __shfl_up_sync(0xFFu, y, o);
            if (t >= o) y += z;
        }
        wt[t] = y;
    }
    __syncthreads();
    int total = wt[7];
    int excl = x - s + (wid ? wt[wid - 1] : 0);

    if (t == 0) {
        if (blk == 0) { st[0] = ((u64)(u32)total << 32) | 2ull; sprefix = 0; }
        else          st[blk] = ((u64)(u32)total << 32) | 1ull;
    }
    if (blk > 0 && t < 32) {
        int running = 0;
        int end = blk;
        while (true) {
            int p = end - 1 - t;
            int f = 0, val = 0;
            if (p >= 0) {
                u64 pk;
                do { pk = st[p]; } while ((pk & 3ull) == 0ull);
                f = (int)(pk & 3ull);
                val = (int)(pk >> 32);
            }
            unsigned m2 = __ballot_sync(0xFFFFFFFFu, p >= 0 && f == 2);
            int contrib;
            bool fin;
            if (m2) {
                int l2 = __ffs(m2) - 1;
                contrib = (t <= l2 && p >= 0) ? val : 0;
                fin = true;
            } else {
                contrib = (p >= 0) ? val : 0;
                fin = false;
            }
#pragma unroll
            for (int o = 16; o; o >>= 1)
                contrib += __shfl_xor_sync(0xFFFFFFFFu, contrib, o);
            running += contrib;
            if (fin) break;
            end -= 32;
            if (end <= 0) break;
        }
        if (t == 0) {
            sprefix = running;
            st[blk] = ((u64)(u32)(running + total) << 32) | 2ull;
        }
    }
    __syncthreads();
    int run = sprefix + excl;
#pragma unroll
    for (int j = 0; j < 16; j++) {
        int idx = base + j;
        if (idx < N) { rs[idx] = run; ptr[idx] = run; }
        run += v[j];
    }
}

// ---------------- K3: reorder(both) + GEMM(dag) ---------------------------------
__global__ void __launch_bounds__(256, 1)
k_reorder_gemmdag(const int* __restrict__ ei_n, const float* __restrict__ ew_n,
                  const float* __restrict__ deg_n, int* __restrict__ ptr_n,
                  int2* __restrict__ ed_n, int En,
                  const int* __restrict__ ei_d, const float* __restrict__ ew_d,
                  const float* __restrict__ deg_d, int* __restrict__ ptr_d,
                  int2* __restrict__ ed_d, int Ed,
                  int reorderBlocks,
                  const float* __restrict__ X, const float* __restrict__ W,
                  __nv_bfloat16* __restrict__ Hb, int N) {
    if ((int)blockIdx.x < reorderBlocks) {
        int stride = reorderBlocks * 256;
        int total = En + Ed;
        for (int i = blockIdx.x * 256 + threadIdx.x; i < total; i += stride) {
            const int* ei; const float* ew; const float* deg; int* ptr;
            int2* ed; int E, e;
            if (i < En) { ei = ei_n; ew = ew_n; deg = deg_n; ptr = ptr_n; ed = ed_n; E = En; e = i; }
            else        { ei = ei_d; ew = ew_d; deg = deg_d; ptr = ptr_d; ed = ed_d; E = Ed; e = i - En; }
            int src = ei[e];
            int dst = ei[E + e];
            float nm = rsqrtf(deg[src]) * ew[e] * rsqrtf(deg[dst]);
            int p = atomicAdd(&ptr[dst], 1);
            ed[p] = make_int2(src, __float_as_int(nm));
        }
    } else {
        gemm_body(X, W, Hb, N, blockIdx.x - reorderBlocks);
    }
}

// ---------------- K4: fused gather + epilogue + (last block) final MLP ----------
__global__ void gather_kernel(const int* __restrict__ rs_n, const int* __restrict__ cnt_n,
                              const int2* __restrict__ ed_n,
                              const __nv_bfloat16* __restrict__ Hn,
                              const float* __restrict__ deg_n,
                              const float* __restrict__ b_n, int Nn, int blocksNet,
                              const int* __restrict__ rs_d, const int* __restrict__ cnt_d,
                              const int2* __restrict__ ed_d,
                              const __nv_bfloat16* __restrict__ Hd,
                              const float* __restrict__ deg_d,
                              const float* __restrict__ b_d,  int Nd,
                              float* __restrict__ acc, int* __restrict__ done,
                              const float* __restrict__ W1, const float* __restrict__ b1,
                              const float* __restrict__ W2, const float* __restrict__ b2,
                              float invNnet, float invNdag, float* __restrict__ out) {
    bool isNet = (int)blockIdx.x < blocksNet;
    const int* rs   = isNet ? rs_n  : rs_d;
    const int* cnt  = isNet ? cnt_n : cnt_d;
    const int2* ed  = isNet ? ed_n  : ed_d;
    const __nv_bfloat16* H = isNet ? Hn : Hd;
    const float* deg = isNet ? deg_n : deg_d;
    const float* bia = isNet ? b_n : b_d;
    int N = isNet ? Nn : Nd;
    float* accBase = isNet ? acc : acc + D;
    int blk  = isNet ? blockIdx.x : blockIdx.x - blocksNet;
    int nblk = isNet ? blocksNet : gridDim.x - blocksNet;

    __shared__ float sacc[D];
    __shared__ int slast;
    int t = threadIdx.x;
    if (t < D) sacc[t] = 0.f;
    __syncthreads();

    int lane = t & 31;
    int warp = blk * 8 + (t >> 5);
    int nwarps = nblk * 8;
    float4 bb = ((const float4*)bia)[lane];
    float4 macc = make_float4(0.f, 0.f, 0.f, 0.f);

    for (int i = warp; i < N; i += nwarps) {
        float dd = 1.0f / deg[i];                      // = dinv^2 (self-loop)
        float4 v = bf16x4_to_f4(((const uint2*)(H + (size_t)i * D))[lane]);
        v.x *= dd; v.y *= dd; v.z *= dd; v.w *= dd;
        int s = rs[i];
        int c = cnt[i];
#pragma unroll 2
        for (int j = 0; j < c; j++) {
            int2 e = __ldg(&ed[s + j]);                // warp-broadcast
            int src = e.x;
            float nm = __int_as_float(e.y);
            float4 hh = bf16x4_to_f4(((const uint2*)(H + (size_t)src * D))[lane]);
            v.x += nm * hh.x; v.y += nm * hh.y;
            v.z += nm * hh.z; v.w += nm * hh.w;
        }
        v.x = fmaxf(v.x + bb.x, 0.f);
        v.y = fmaxf(v.y + bb.y, 0.f);
        v.z = fmaxf(v.z + bb.z, 0.f);
        v.w = fmaxf(v.w + bb.w, 0.f);
        float ss = v.x * v.x + v.y * v.y + v.z * v.z + v.w * v.w;
#pragma unroll
        for (int o = 16; o; o >>= 1) ss += __shfl_xor_sync(0xFFFFFFFFu, ss, o);
        float scale = 1.0f / fmaxf(sqrtf(ss), 1e-12f);
        macc.x += v.x * scale;
        macc.y += v.y * scale;
        macc.z += v.z * scale;
        macc.w += v.w * scale;
    }
    float* so = sacc + lane * 4;
    atomicAdd(so + 0, macc.x);
    atomicAdd(so + 1, macc.y);
    atomicAdd(so + 2, macc.z);
    atomicAdd(so + 3, macc.w);
    __syncthreads();
    if (t < D) atomicAdd(accBase + t, sacc[t]);

    // ---- last block runs the final MLP ----
    __syncthreads();
    if (t == 0) {
        __threadfence();
        slast = (atomicAdd(done, 1) == (int)gridDim.x - 1);
    }
    __syncthreads();
    if (slast) {
        __threadfence();
        __shared__ float cvec[256];
        __shared__ float h1[64];
        cvec[t] = __ldcg(&acc[t]) * (t < 128 ? invNnet : invNdag);
        __syncthreads();
        if (t < 64) {
            float s = b1[t];
#pragma unroll 8
            for (int i = 0; i < 256; i++) s += cvec[i] * W1[i * 64 + t];
            h1[t] = fmaxf(s, 0.f);
        }
        __syncthreads();
        if (t == 0) {
            float s = b2[0];
#pragma unroll
            for (int j = 0; j < 64; j++) s += h1[j] * W2[j];
            out[0] = s;
        }
    }
}

// ---------------- launch ----------------------------------------------------------
extern "C" void kernel_launch(void* const* d_in, const int* in_sizes, int n_in,
                              void* d_out, int out_size) {
    const float* net_feat = (const float*)d_in[0];
    const int*   net_ei   = (const int*)  d_in[1];
    const float* net_ew   = (const float*)d_in[2];
    const float* dag_feat = (const float*)d_in[3];
    const int*   dag_ei   = (const int*)  d_in[4];
    const float* dag_ew   = (const float*)d_in[5];
    const float* W_net    = (const float*)d_in[6];
    const float* b_net    = (const float*)d_in[7];
    const float* W_dag    = (const float*)d_in[8];
    const float* b_dag    = (const float*)d_in[9];
    const float* W1       = (const float*)d_in[10];
    const float* b1       = (const float*)d_in[11];
    const float* W2       = (const float*)d_in[12];
    const float* b2       = (const float*)d_in[13];
    float* out = (float*)d_out;

    const int N_net = in_sizes[0] / D;
    const int E_net = in_sizes[2];
    const int N_dag = in_sizes[3] / D;
    const int E_dag = in_sizes[5];

    void *p;
    cudaGetSymbolAddress(&p, g_h_net);   __nv_bfloat16* h_net = (__nv_bfloat16*)p;
    cudaGetSymbolAddress(&p, g_h_dag);   __nv_bfloat16* h_dag = (__nv_bfloat16*)p;
    cudaGetSymbolAddress(&p, g_deg_net); float* deg_net = (float*)p;
    cudaGetSymbolAddress(&p, g_deg_dag); float* deg_dag = (float*)p;
    cudaGetSymbolAddress(&p, g_cnt_net); int* cnt_net = (int*)p;
    cudaGetSymbolAddress(&p, g_cnt_dag); int* cnt_dag = (int*)p;
    cudaGetSymbolAddress(&p, g_rs_net);  int* rs_net = (int*)p;
    cudaGetSymbolAddress(&p, g_rs_dag);  int* rs_dag = (int*)p;
    cudaGetSymbolAddress(&p, g_ptr_net); int* ptr_net = (int*)p;
    cudaGetSymbolAddress(&p, g_ptr_dag); int* ptr_dag = (int*)p;
    cudaGetSymbolAddress(&p, g_ed_net);  int2* ed_net = (int2*)p;
    cudaGetSymbolAddress(&p, g_ed_dag);  int2* ed_dag = (int2*)p;
    cudaGetSymbolAddress(&p, g_status_net); u64* st_net = (u64*)p;
    cudaGetSymbolAddress(&p, g_status_dag); u64* st_dag = (u64*)p;
    cudaGetSymbolAddress(&p, g_done);    int* done = (int*)p;
    cudaGetSymbolAddress(&p, g_acc);     float* acc = (float*)p;

    const int smem_gemm = 128 * 1024;
    cudaFuncSetAttribute(k_hist_gemmnet,
                         cudaFuncAttributeMaxDynamicSharedMemorySize, smem_gemm);
    cudaFuncSetAttribute(k_reorder_gemmdag,
                         cudaFuncAttributeMaxDynamicSharedMemorySize, smem_gemm);

    const int nbN = (N_net + 4095) / 4096;
    const int nbD = (N_dag + 4095) / 4096;

    // K0: init
    init_kernel<<<128, 256>>>(deg_net, cnt_net, N_net, deg_dag, cnt_dag, N_dag,
                              st_net, st_dag, acc, done);

    // K1: histogram(both) + GEMM(net)
    const int histBlocks = 128;
    k_hist_gemmnet<<<histBlocks + (N_net + 127) / 128, 256, smem_gemm>>>(
        net_ei, net_ew, deg_net, cnt_net, E_net,
        dag_ei, dag_ew, deg_dag, cnt_dag, E_dag,
        histBlocks, net_feat, W_net, h_net, N_net);

    // K2: single-pass scan (both graphs)
    scan_kernel<<<nbN + nbD, 256>>>(cnt_net, rs_net, ptr_net, N_net, nbN,
                                    cnt_dag, rs_dag, ptr_dag, N_dag,
                                    st_net, st_dag);

    // K3: reorder(both) + GEMM(dag)
    const int reorderBlocks = 128;
    k_reorder_gemmdag<<<reorderBlocks + (N_dag + 127) / 128, 256, smem_gemm>>>(
        net_ei, net_ew, deg_net, ptr_net, ed_net, E_net,
        dag_ei, dag_ew, deg_dag, ptr_dag, ed_dag, E_dag,
        reorderBlocks, dag_feat, W_dag, h_dag, N_dag);

    // K4: fused gather + epilogue + final MLP (one wave)
    const int blocksNet = 394, blocksDag = 198;
    gather_kernel<<<blocksNet + blocksDag, 256>>>(
        rs_net, cnt_net, ed_net, h_net, deg_net, b_net, N_net, blocksNet,
        rs_dag, cnt_dag, ed_dag, h_dag, deg_dag, b_dag, N_dag, acc, done,
        W1, b1, W2, b2, 1.0f / (float)N_net, 1.0f / (float)N_dag, out);
}

// round 8
// speedup vs baseline: 3.7801x; 1.1224x over previous
#include <cuda_runtime.h>
#include <cuda_bf16.h>

#define D 128
#define MAXN_NET 100000
#define MAXN_DAG 50000
#define MAXE_NET 600000
#define MAXE_DAG 400000

typedef unsigned long long u64;
typedef unsigned int u32;

// ---------------- device scratch (allocation-free rule: __device__ globals) ---
__device__ __align__(16) __nv_bfloat16 g_h_net[MAXN_NET * D];
__device__ __align__(16) __nv_bfloat16 g_h_dag[MAXN_DAG * D];
__device__ __align__(16) float2 g_dc_net[MAXN_NET];   // (deg, cnt-as-float)
__device__ __align__(16) float2 g_dc_dag[MAXN_DAG];
__device__ int   g_rs_net[MAXN_NET];
__device__ int   g_rs_dag[MAXN_DAG];
__device__ int   g_cnt_net[MAXN_NET];
__device__ int   g_cnt_dag[MAXN_DAG];
__device__ int   g_ptr_net[MAXN_NET];
__device__ int   g_ptr_dag[MAXN_DAG];
__device__ __align__(16) int2 g_ed_net[MAXE_NET];     // (src, norm-as-int)
__device__ __align__(16) int2 g_ed_dag[MAXE_DAG];
__device__ u64   g_status_net[64];                    // lookback (value<<32)|flag
__device__ u64   g_status_dag[64];
__device__ int   g_done;
__device__ __align__(16) float g_acc[2 * D];

// ---------------- helpers ------------------------------------------------------
__device__ __forceinline__ u32 pack_bf16x2(float lo, float hi) {
    __nv_bfloat162 p = __float22bfloat162_rn(make_float2(lo, hi));
    return *reinterpret_cast<u32*>(&p);
}
__device__ __forceinline__ float4 bf16x4_to_f4(uint2 u) {
    __nv_bfloat162 p0 = *reinterpret_cast<__nv_bfloat162*>(&u.x);
    __nv_bfloat162 p1 = *reinterpret_cast<__nv_bfloat162*>(&u.y);
    float2 f0 = __bfloat1622float2(p0);
    float2 f1 = __bfloat1622float2(p1);
    return make_float4(f0.x, f0.y, f1.x, f1.y);
}
__device__ __forceinline__ u32 f2tf32(float f) {
    u32 r;
    asm("cvt.rna.tf32.f32 %0, %1;" : "=r"(r) : "f"(f));
    return r;
}
__device__ __forceinline__ uint4 f4_to_tf32x4(float4 v) {
    return make_uint4(f2tf32(v.x), f2tf32(v.y), f2tf32(v.z), f2tf32(v.w));
}
__device__ __forceinline__ void ldsm_x4(u32& r0, u32& r1, u32& r2, u32& r3, u32 a) {
    asm volatile("ldmatrix.sync.aligned.m8n8.x4.shared.b16 {%0,%1,%2,%3}, [%4];"
                 : "=r"(r0), "=r"(r1), "=r"(r2), "=r"(r3) : "r"(a));
}
__device__ __forceinline__ void mma_tf32(float c[4], u32 a0, u32 a1, u32 a2, u32 a3,
                                         u32 b0, u32 b1) {
    asm volatile(
        "mma.sync.aligned.m16n8k8.row.col.f32.tf32.tf32.f32 "
        "{%0,%1,%2,%3}, {%4,%5,%6,%7}, {%8,%9}, {%0,%1,%2,%3};"
        : "+f"(c[0]), "+f"(c[1]), "+f"(c[2]), "+f"(c[3])
        : "r"(a0), "r"(a1), "r"(a2), "r"(a3), "r"(b0), "r"(b1));
}
__device__ __forceinline__ void red_add_v2(float2* p, float a, float b) {
    asm volatile("red.global.add.v2.f32 [%0], {%1,%2};"
                 :: "l"(p), "f"(a), "f"(b) : "memory");
}

// ---------------- TF32 GEMM body: 64-row tile (96KB smem, 2 blocks/SM) ---------
// H[N,128] = X[N,128] @ W[128,128]; 256 thr = 8 warps (4 m x 2 n).
__device__ void gemm_body(const float* __restrict__ X, const float* __restrict__ W,
                          __nv_bfloat16* __restrict__ Hb, int N, int bid) {
    extern __shared__ char smem[];
    char* sA = smem;                 // 64 rows x 512B = 32KB
    char* sB = smem + 32 * 1024;     // 128 n-rows x 512B = 64KB (W transposed)
    const int tid = threadIdx.x;
    const int row0 = bid * 64;

    // fill Wt (transpose W[k][n] -> sB[n][k]), coalesced over n
#pragma unroll
    for (int i = 0; i < 16; i++) {
        int idx = i * 256 + tid;
        int n = idx & 127, kc = idx >> 7;          // kc = k-chunk (4 floats)
        uint4 v = make_uint4(f2tf32(W[(kc * 4 + 0) * D + n]),
                             f2tf32(W[(kc * 4 + 1) * D + n]),
                             f2tf32(W[(kc * 4 + 2) * D + n]),
                             f2tf32(W[(kc * 4 + 3) * D + n]));
        *(uint4*)(sB + n * 512 + ((kc ^ (n & 7)) << 4)) = v;
    }
    // fill A (64 X rows, zero-pad past N)
#pragma unroll
    for (int i = 0; i < 8; i++) {
        int idx = i * 256 + tid;
        int r = idx >> 5, ch = idx & 31;
        int grow = row0 + r;
        float4 f = make_float4(0.f, 0.f, 0.f, 0.f);
        if (grow < N) f = ((const float4*)X)[grow * 32 + ch];
        *(uint4*)(sA + r * 512 + ((ch ^ (r & 7)) << 4)) = f4_to_tf32x4(f);
    }
    __syncthreads();

    const int lane = tid & 31;
    const int w = tid >> 5;
    const int m0 = (w >> 1) * 16;     // 4 warp-rows x 16
    const int n0 = (w & 1) * 64;      // 2 warp-cols x 64
    const int sub = lane >> 3, rowin = lane & 7;

    float c[8][4];
#pragma unroll
    for (int nt = 0; nt < 8; nt++)
#pragma unroll
        for (int k = 0; k < 4; k++) c[nt][k] = 0.f;

#pragma unroll
    for (int ks = 0; ks < 16; ks++) {              // k = ks*8 .. ks*8+7
        u32 a[4];
        {
            int r = m0 + (sub & 1) * 8 + rowin;
            int ch = ks * 2 + (sub >> 1);
            u32 addr = (u32)__cvta_generic_to_shared(
                sA + r * 512 + ((ch ^ (r & 7)) << 4));
            ldsm_x4(a[0], a[1], a[2], a[3], addr);
        }
        u32 b[4][4];
#pragma unroll
        for (int q = 0; q < 4; q++) {
            int n = n0 + q * 16 + (sub >> 1) * 8 + rowin;
            int ch = ks * 2 + (sub & 1);
            u32 addr = (u32)__cvta_generic_to_shared(
                sB + n * 512 + ((ch ^ (n & 7)) << 4));
            ldsm_x4(b[q][0], b[q][1], b[q][2], b[q][3], addr);
        }
#pragma unroll
        for (int nt = 0; nt < 8; nt++)
            mma_tf32(c[nt], a[0], a[1], a[2], a[3],
                     b[nt >> 1][(nt & 1) * 2], b[nt >> 1][(nt & 1) * 2 + 1]);
    }

    // epilogue: fp32 acc -> bf16 store (guarded)
#pragma unroll
    for (int nt = 0; nt < 8; nt++) {
        int r = m0 + (lane >> 2);
        int col = n0 + nt * 8 + (lane & 3) * 2;
        int g0 = row0 + r, g1 = g0 + 8;
        if (g0 < N)
            *(u32*)(Hb + (size_t)g0 * D + col) = pack_bf16x2(c[nt][0], c[nt][1]);
        if (g1 < N)
            *(u32*)(Hb + (size_t)g1 * D + col) = pack_bf16x2(c[nt][2], c[nt][3]);
    }
}

// ---------------- K0: init -----------------------------------------------------
__global__ void init_kernel(float2* dc_n, int Nn, float2* dc_d, int Nd,
                            u64* st_n, u64* st_d, float* acc, int* done) {
    int i = blockIdx.x * blockDim.x + threadIdx.x;
    int stride = gridDim.x * blockDim.x;
    for (; i < Nn; i += stride) {
        dc_n[i] = make_float2(1.0f, 0.0f);                // self-loop weight 1
        if (i < Nd) dc_d[i] = make_float2(1.0f, 0.0f);
        if (i < 64) { st_n[i] = 0ull; st_d[i] = 0ull; }
        if (i < 2 * D) acc[i] = 0.f;
        if (i == 0) *done = 0;
    }
}

// ---------------- K1: hist(both) + GEMM(net) -----------------------------------
__global__ void __launch_bounds__(256, 2)
k_hist_gemmnet(const int* __restrict__ ei_n, const float* __restrict__ ew_n,
               float2* __restrict__ dc_n, int En,
               const int* __restrict__ ei_d, const float* __restrict__ ew_d,
               float2* __restrict__ dc_d, int Ed,
               int histBlocks,
               const float* __restrict__ X, const float* __restrict__ W,
               __nv_bfloat16* __restrict__ Hb, int N) {
    if ((int)blockIdx.x < histBlocks) {
        int stride = histBlocks * 256;
        int total = En + Ed;
        for (int i = blockIdx.x * 256 + threadIdx.x; i < total; i += stride) {
            if (i < En) {
                int dst = ei_n[En + i];
                red_add_v2(&dc_n[dst], ew_n[i], 1.0f);
            } else {
                int e = i - En;
                int dst = ei_d[Ed + e];
                red_add_v2(&dc_d[dst], ew_d[e], 1.0f);
            }
        }
    } else {
        gemm_body(X, W, Hb, N, blockIdx.x - histBlocks);
    }
}

// ---------------- K2: single-pass scan, decoupled lookback, both graphs --------
__global__ void scan_kernel(const float2* __restrict__ dc_n, int* __restrict__ rs_n,
                            int* __restrict__ cnt_n, int* __restrict__ ptr_n,
                            int Nn, int nbN,
                            const float2* __restrict__ dc_d, int* __restrict__ rs_d,
                            int* __restrict__ cnt_d, int* __restrict__ ptr_d, int Nd,
                            u64* st_n, u64* st_d) {
    const float2* dc; int* rs; int* cnto; int* ptr; int N, blk;
    volatile u64* st;
    if ((int)blockIdx.x < nbN) {
        dc = dc_n; rs = rs_n; cnto = cnt_n; ptr = ptr_n; N = Nn; blk = blockIdx.x;
        st = (volatile u64*)st_n;
    } else {
        dc = dc_d; rs = rs_d; cnto = cnt_d; ptr = ptr_d; N = Nd; blk = blockIdx.x - nbN;
        st = (volatile u64*)st_d;
    }

    int t = threadIdx.x;
    int base = blk * 4096 + t * 16;
    int v[16], s = 0;
#pragma unroll
    for (int j = 0; j < 16; j++) {
        int idx = base + j;
        v[j] = (idx < N) ? (int)dc[idx].y : 0;
        s += v[j];
    }
    int lane = t & 31, wid = t >> 5;
    int x = s;
#pragma unroll
    for (int o = 1; o < 32; o <<= 1) {
        int y = __shfl_up_sync(0xFFFFFFFFu, x, o);
        if (lane >= o) x += y;
    }
    __shared__ int wt[8];
    __shared__ int sprefix;
    if (lane == 31) wt[wid] = x;
    __syncthreads();
    if (t < 8) {
        int y = wt[t];
#pragma unroll
        for (int o = 1; o < 8; o <<= 1) {
            int z = __shfl_up_sync(0xFFu, y, o);
            if (t >= o) y += z;
        }
        wt[t] = y;
    }
    __syncthreads();
    int total = wt[7];
    int excl = x - s + (wid ? wt[wid - 1] : 0);

    if (t == 0) {
        if (blk == 0) { st[0] = ((u64)(u32)total << 32) | 2ull; sprefix = 0; }
        else          st[blk] = ((u64)(u32)total << 32) | 1ull;
    }
    if (blk > 0 && t < 32) {
        int running = 0;
        int end = blk;
        while (true) {
            int p = end - 1 - t;
            int f = 0, val = 0;
            if (p >= 0) {
                u64 pk;
                do { pk = st[p]; } while ((pk & 3ull) == 0ull);
                f = (int)(pk & 3ull);
                val = (int)(pk >> 32);
            }
            unsigned m2 = __ballot_sync(0xFFFFFFFFu, p >= 0 && f == 2);
            int contrib;
            bool fin;
            if (m2) {
                int l2 = __ffs(m2) - 1;
                contrib = (t <= l2 && p >= 0) ? val : 0;
                fin = true;
            } else {
                contrib = (p >= 0) ? val : 0;
                fin = false;
            }
#pragma unroll
            for (int o = 16; o; o >>= 1)
                contrib += __shfl_xor_sync(0xFFFFFFFFu, contrib, o);
            running += contrib;
            if (fin) break;
            end -= 32;
            if (end <= 0) break;
        }
        if (t == 0) {
            sprefix = running;
            st[blk] = ((u64)(u32)(running + total) << 32) | 2ull;
        }
    }
    __syncthreads();
    int run = sprefix + excl;
#pragma unroll
    for (int j = 0; j < 16; j++) {
        int idx = base + j;
        if (idx < N) { rs[idx] = run; cnto[idx] = v[j]; ptr[idx] = run; }
        run += v[j];
    }
}

// ---------------- K3: reorder(both) + GEMM(dag) ---------------------------------
__global__ void __launch_bounds__(256, 2)
k_reorder_gemmdag(const int* __restrict__ ei_n, const float* __restrict__ ew_n,
                  const float2* __restrict__ dc_n, int* __restrict__ ptr_n,
                  int2* __restrict__ ed_n, int En,
                  const int* __restrict__ ei_d, const float* __restrict__ ew_d,
                  const float2* __restrict__ dc_d, int* __restrict__ ptr_d,
                  int2* __restrict__ ed_d, int Ed,
                  int reorderBlocks,
                  const float* __restrict__ X, const float* __restrict__ W,
                  __nv_bfloat16* __restrict__ Hb, int N) {
    if ((int)blockIdx.x < reorderBlocks) {
        int stride = reorderBlocks * 256;
        int total = En + Ed;
        for (int i = blockIdx.x * 256 + threadIdx.x; i < total; i += stride) {
            const int* ei; const float* ew; const float2* dc; int* ptr;
            int2* ed; int E, e;
            if (i < En) { ei = ei_n; ew = ew_n; dc = dc_n; ptr = ptr_n; ed = ed_n; E = En; e = i; }
            else        { ei = ei_d; ew = ew_d; dc = dc_d; ptr = ptr_d; ed = ed_d; E = Ed; e = i - En; }
            int src = ei[e];
            int dst = ei[E + e];
            float nm = rsqrtf(dc[src].x) * ew[e] * rsqrtf(dc[dst].x);
            int p = atomicAdd(&ptr[dst], 1);
            ed[p] = make_int2(src, __float_as_int(nm));
        }
    } else {
        gemm_body(X, W, Hb, N, blockIdx.x - reorderBlocks);
    }
}

// ---------------- K4: fused gather + epilogue + (last block) final MLP ----------
__global__ void gather_kernel(const int* __restrict__ rs_n, const int* __restrict__ cnt_n,
                              const int2* __restrict__ ed_n,
                              const __nv_bfloat16* __restrict__ Hn,
                              const float2* __restrict__ dc_n,
                              const float* __restrict__ b_n, int Nn, int blocksNet,
                              const int* __restrict__ rs_d, const int* __restrict__ cnt_d,
                              const int2* __restrict__ ed_d,
                              const __nv_bfloat16* __restrict__ Hd,
                              const float2* __restrict__ dc_d,
                              const float* __restrict__ b_d,  int Nd,
                              float* __restrict__ acc, int* __restrict__ done,
                              const float* __restrict__ W1, const float* __restrict__ b1,
                              const float* __restrict__ W2, const float* __restrict__ b2,
                              float invNnet, float invNdag, float* __restrict__ out) {
    bool isNet = (int)blockIdx.x < blocksNet;
    const int* rs   = isNet ? rs_n  : rs_d;
    const int* cnt  = isNet ? cnt_n : cnt_d;
    const int2* ed  = isNet ? ed_n  : ed_d;
    const __nv_bfloat16* H = isNet ? Hn : Hd;
    const float2* dc = isNet ? dc_n : dc_d;
    const float* bia = isNet ? b_n : b_d;
    int N = isNet ? Nn : Nd;
    float* accBase = isNet ? acc : acc + D;
    int blk  = isNet ? blockIdx.x : blockIdx.x - blocksNet;
    int nblk = isNet ? blocksNet : gridDim.x - blocksNet;

    __shared__ float sacc[D];
    __shared__ int slast;
    int t = threadIdx.x;
    if (t < D) sacc[t] = 0.f;
    __syncthreads();

    int lane = t & 31;
    int warp = blk * 8 + (t >> 5);
    int nwarps = nblk * 8;
    float4 bb = ((const float4*)bia)[lane];
    float4 macc = make_float4(0.f, 0.f, 0.f, 0.f);

    for (int i = warp; i < N; i += nwarps) {
        float dd = 1.0f / dc[i].x;                     // = dinv^2 (self-loop)
        float4 v = bf16x4_to_f4(((const uint2*)(H + (size_t)i * D))[lane]);
        v.x *= dd; v.y *= dd; v.z *= dd; v.w *= dd;
        int s = rs[i];
        int c = cnt[i];
        int j = 0;
        // unroll-4: 4 independent edge loads, then 4 independent row loads
        for (; j + 4 <= c; j += 4) {
            int2 e0 = __ldg(&ed[s + j + 0]);
            int2 e1 = __ldg(&ed[s + j + 1]);
            int2 e2 = __ldg(&ed[s + j + 2]);
            int2 e3 = __ldg(&ed[s + j + 3]);
            float4 h0 = bf16x4_to_f4(((const uint2*)(H + (size_t)e0.x * D))[lane]);
            float4 h1 = bf16x4_to_f4(((const uint2*)(H + (size_t)e1.x * D))[lane]);
            float4 h2 = bf16x4_to_f4(((const uint2*)(H + (size_t)e2.x * D))[lane]);
            float4 h3 = bf16x4_to_f4(((const uint2*)(H + (size_t)e3.x * D))[lane]);
            float n0 = __int_as_float(e0.y), n1 = __int_as_float(e1.y);
            float n2 = __int_as_float(e2.y), n3 = __int_as_float(e3.y);
            v.x += n0 * h0.x + n1 * h1.x + n2 * h2.x + n3 * h3.x;
            v.y += n0 * h0.y + n1 * h1.y + n2 * h2.y + n3 * h3.y;
            v.z += n0 * h0.z + n1 * h1.z + n2 * h2.z + n3 * h3.z;
            v.w += n0 * h0.w + n1 * h1.w + n2 * h2.w + n3 * h3.w;
        }
        for (; j < c; j++) {
            int2 e = __ldg(&ed[s + j]);
            float nm = __int_as_float(e.y);
            float4 hh = bf16x4_to_f4(((const uint2*)(H + (size_t)e.x * D))[lane]);
            v.x += nm * hh.x; v.y += nm * hh.y;
            v.z += nm * hh.z; v.w += nm * hh.w;
        }
        v.x = fmaxf(v.x + bb.x, 0.f);
        v.y = fmaxf(v.y + bb.y, 0.f);
        v.z = fmaxf(v.z + bb.z, 0.f);
        v.w = fmaxf(v.w + bb.w, 0.f);
        float ss = v.x * v.x + v.y * v.y + v.z * v.z + v.w * v.w;
#pragma unroll
        for (int o = 16; o; o >>= 1) ss += __shfl_xor_sync(0xFFFFFFFFu, ss, o);
        float scale = 1.0f / fmaxf(sqrtf(ss), 1e-12f);
        macc.x += v.x * scale;
        macc.y += v.y * scale;
        macc.z += v.z * scale;
        macc.w += v.w * scale;
    }
    float* so = sacc + lane * 4;
    atomicAdd(so + 0, macc.x);
    atomicAdd(so + 1, macc.y);
    atomicAdd(so + 2, macc.z);
    atomicAdd(so + 3, macc.w);
    __syncthreads();
    if (t < D) atomicAdd(accBase + t, sacc[t]);

    // ---- last block runs the final MLP ----
    __syncthreads();
    if (t == 0) {
        __threadfence();
        slast = (atomicAdd(done, 1) == (int)gridDim.x - 1);
    }
    __syncthreads();
    if (slast) {
        __threadfence();
        __shared__ float cvec[256];
        __shared__ float h1[64];
        cvec[t] = __ldcg(&acc[t]) * (t < 128 ? invNnet : invNdag);
        __syncthreads();
        if (t < 64) {
            float s = b1[t];
#pragma unroll 8
            for (int i = 0; i < 256; i++) s += cvec[i] * W1[i * 64 + t];
            h1[t] = fmaxf(s, 0.f);
        }
        __syncthreads();
        if (t == 0) {
            float s = b2[0];
#pragma unroll
            for (int j = 0; j < 64; j++) s += h1[j] * W2[j];
            out[0] = s;
        }
    }
}

// ---------------- launch ----------------------------------------------------------
extern "C" void kernel_launch(void* const* d_in, const int* in_sizes, int n_in,
                              void* d_out, int out_size) {
    const float* net_feat = (const float*)d_in[0];
    const int*   net_ei   = (const int*)  d_in[1];
    const float* net_ew   = (const float*)d_in[2];
    const float* dag_feat = (const float*)d_in[3];
    const int*   dag_ei   = (const int*)  d_in[4];
    const float* dag_ew   = (const float*)d_in[5];
    const float* W_net    = (const float*)d_in[6];
    const float* b_net    = (const float*)d_in[7];
    const float* W_dag    = (const float*)d_in[8];
    const float* b_dag    = (const float*)d_in[9];
    const float* W1       = (const float*)d_in[10];
    const float* b1       = (const float*)d_in[11];
    const float* W2       = (const float*)d_in[12];
    const float* b2       = (const float*)d_in[13];
    float* out = (float*)d_out;

    const int N_net = in_sizes[0] / D;
    const int E_net = in_sizes[2];
    const int N_dag = in_sizes[3] / D;
    const int E_dag = in_sizes[5];

    void *p;
    cudaGetSymbolAddress(&p, g_h_net);   __nv_bfloat16* h_net = (__nv_bfloat16*)p;
    cudaGetSymbolAddress(&p, g_h_dag);   __nv_bfloat16* h_dag = (__nv_bfloat16*)p;
    cudaGetSymbolAddress(&p, g_dc_net);  float2* dc_net = (float2*)p;
    cudaGetSymbolAddress(&p, g_dc_dag);  float2* dc_dag = (float2*)p;
    cudaGetSymbolAddress(&p, g_rs_net);  int* rs_net = (int*)p;
    cudaGetSymbolAddress(&p, g_rs_dag);  int* rs_dag = (int*)p;
    cudaGetSymbolAddress(&p, g_cnt_net); int* cnt_net = (int*)p;
    cudaGetSymbolAddress(&p, g_cnt_dag); int* cnt_dag = (int*)p;
    cudaGetSymbolAddress(&p, g_ptr_net); int* ptr_net = (int*)p;
    cudaGetSymbolAddress(&p, g_ptr_dag); int* ptr_dag = (int*)p;
    cudaGetSymbolAddress(&p, g_ed_net);  int2* ed_net = (int2*)p;
    cudaGetSymbolAddress(&p, g_ed_dag);  int2* ed_dag = (int2*)p;
    cudaGetSymbolAddress(&p, g_status_net); u64* st_net = (u64*)p;
    cudaGetSymbolAddress(&p, g_status_dag); u64* st_dag = (u64*)p;
    cudaGetSymbolAddress(&p, g_done);    int* done = (int*)p;
    cudaGetSymbolAddress(&p, g_acc);     float* acc = (float*)p;

    const int smem_gemm = 96 * 1024;
    cudaFuncSetAttribute(k_hist_gemmnet,
                         cudaFuncAttributeMaxDynamicSharedMemorySize, smem_gemm);
    cudaFuncSetAttribute(k_reorder_gemmdag,
                         cudaFuncAttributeMaxDynamicSharedMemorySize, smem_gemm);

    const int nbN = (N_net + 4095) / 4096;
    const int nbD = (N_dag + 4095) / 4096;

    // K0: init
    init_kernel<<<128, 256>>>(dc_net, N_net, dc_dag, N_dag, st_net, st_dag, acc, done);

    // K1: histogram(both, vector RED) + GEMM(net)
    const int histBlocks = 148;
    k_hist_gemmnet<<<histBlocks + (N_net + 63) / 64, 256, smem_gemm>>>(
        net_ei, net_ew, dc_net, E_net,
        dag_ei, dag_ew, dc_dag, E_dag,
        histBlocks, net_feat, W_net, h_net, N_net);

    // K2: single-pass scan (both graphs)
    scan_kernel<<<nbN + nbD, 256>>>(dc_net, rs_net, cnt_net, ptr_net, N_net, nbN,
                                    dc_dag, rs_dag, cnt_dag, ptr_dag, N_dag,
                                    st_net, st_dag);

    // K3: reorder(both) + GEMM(dag)
    const int reorderBlocks = 148;
    k_reorder_gemmdag<<<reorderBlocks + (N_dag + 63) / 64, 256, smem_gemm>>>(
        net_ei, net_ew, dc_net, ptr_net, ed_net, E_net,
        dag_ei, dag_ew, dc_dag, ptr_dag, ed_dag, E_dag,
        reorderBlocks, dag_feat, W_dag, h_dag, N_dag);

    // K4: fused gather + epilogue + final MLP
    const int blocksNet = 540, blocksDag = 348;
    gather_kernel<<<blocksNet + blocksDag, 256>>>(
        rs_net, cnt_net, ed_net, h_net, dc_net, b_net, N_net, blocksNet,
        rs_dag, cnt_dag, ed_dag, h_dag, dc_dag, b_dag, N_dag, acc, done,
        W1, b1, W2, b2, 1.0f / (float)N_net, 1.0f / (float)N_dag, out);
}